// round 1
// baseline (speedup 1.0000x reference)
#include <cuda_runtime.h>
#include <cstdint>
#include <cstddef>

// Problem constants (fixed by reference setup)
#define LSEQ   2048
#define BATCH  2
#define HEADS  16
#define DHEAD  64
#define DMODEL 1024
#define MROWS  (BATCH * LSEQ)   // 4096
#define BH     (BATCH * HEADS)  // 32

// Scratch (allowed: __device__ globals)
__device__ float g_Q[BH * LSEQ * DHEAD];
__device__ float g_K[BH * LSEQ * DHEAD];
__device__ float g_V[BH * LSEQ * DHEAD];
__device__ float g_Y[MROWS * DMODEL];

// FFMA-only exp: exp(x) = 2^(x*log2e), |x| is small here (A ~ N(0, 1/64))
__device__ __forceinline__ float fast_exp(float x) {
    float y = x * 1.4426950408889634f;
    float z = y + 12582912.0f;               // round-to-nearest-int magic
    int   n = __float_as_int(z) - 0x4B400000;
    float f = y - (z - 12582912.0f);         // f in [-0.5, 0.5]
    float p = 1.3333558146e-3f;
    p = fmaf(p, f, 9.6181291076e-3f);
    p = fmaf(p, f, 5.5504108665e-2f);
    p = fmaf(p, f, 2.4022650696e-1f);
    p = fmaf(p, f, 6.9314718056e-1f);
    p = fmaf(p, f, 1.0f);
    return __int_as_float(__float_as_int(p) + (n << 23));
}

// ---------------------------------------------------------------------------
// Shared SGEMM core: C_tile[128x128] = A[row0:+128, 0:1024] * B[0:1024, col0:+128]
// A row-major lda=1024, B row-major ldb given. 256 threads, 8x8 per thread,
// BK=8, double-buffered smem with register prefetch.
// ---------------------------------------------------------------------------
__device__ __forceinline__ void gemm_core(
    const float* __restrict__ A, const float* __restrict__ B, int ldb,
    int row0, int col0,
    float (*As)[8][128], float (*Bs)[8][128],
    float acc[8][8])
{
    const int tid = threadIdx.x;
    const int ty = tid >> 4, tx = tid & 15;
    const int arow = tid >> 1, acol = (tid & 1) << 2;
    const int brow = tid >> 5, bcol = (tid & 31) << 2;
    const float* Ag = A + (size_t)(row0 + arow) * DMODEL + acol;
    const float* Bg = B + (size_t)brow * ldb + col0 + bcol;

    float4 av = *(const float4*)Ag;
    float4 bv = *(const float4*)Bg;
    As[0][acol + 0][arow] = av.x;
    As[0][acol + 1][arow] = av.y;
    As[0][acol + 2][arow] = av.z;
    As[0][acol + 3][arow] = av.w;
    *(float4*)&Bs[0][brow][bcol] = bv;
    __syncthreads();

    #pragma unroll
    for (int i = 0; i < 8; ++i)
        #pragma unroll
        for (int j = 0; j < 8; ++j) acc[i][j] = 0.f;

    int buf = 0;
    #pragma unroll 1
    for (int kt = 0; kt < DMODEL / 8; ++kt) {
        if (kt + 1 < DMODEL / 8) {
            av = *(const float4*)(Ag + (kt + 1) * 8);
            bv = *(const float4*)(Bg + (size_t)(kt + 1) * 8 * ldb);
        }
        #pragma unroll
        for (int kk = 0; kk < 8; ++kk) {
            float a[8], b[8];
            *(float4*)&a[0] = *(const float4*)&As[buf][kk][ty * 8];
            *(float4*)&a[4] = *(const float4*)&As[buf][kk][ty * 8 + 4];
            *(float4*)&b[0] = *(const float4*)&Bs[buf][kk][tx * 8];
            *(float4*)&b[4] = *(const float4*)&Bs[buf][kk][tx * 8 + 4];
            #pragma unroll
            for (int i = 0; i < 8; ++i)
                #pragma unroll
                for (int j = 0; j < 8; ++j)
                    acc[i][j] = fmaf(a[i], b[j], acc[i][j]);
        }
        if (kt + 1 < DMODEL / 8) {
            buf ^= 1;
            As[buf][acol + 0][arow] = av.x;
            As[buf][acol + 1][arow] = av.y;
            As[buf][acol + 2][arow] = av.z;
            As[buf][acol + 3][arow] = av.w;
            *(float4*)&Bs[buf][brow][bcol] = bv;
            __syncthreads();
        }
    }
}

// ---------------------------------------------------------------------------
// Kernel 1: qk = (X @ W_qk)/32, per-head LayerNorm(64) on q and k halves,
// write Q,K in [bh, l, 64] layout. Grid: (heads=16, mtiles=32).
// Block column range = head h's 128 cols (q: 0..63, k: 64..127).
// ---------------------------------------------------------------------------
__global__ __launch_bounds__(256) void k_qk_ln(
    const float* __restrict__ X, const float* __restrict__ Wqk,
    const float* __restrict__ qsc, const float* __restrict__ qbi,
    const float* __restrict__ ksc, const float* __restrict__ kbi)
{
    __shared__ float As[2][8][128], Bs[2][8][128];
    float acc[8][8];
    const int h = blockIdx.x;
    const int row0 = blockIdx.y * 128;
    gemm_core(X, Wqk, 2 * HEADS * DHEAD, row0, h * 128, As, Bs, acc);

    const int tid = threadIdx.x, ty = tid >> 4, tx = tid & 15;
    const bool isq = (tx < 8);
    const int dbase = (tx & 7) * 8;
    const float* sc = isq ? qsc : ksc;
    const float* bi = isq ? qbi : kbi;
    float scv[8], biv[8];
    #pragma unroll
    for (int j = 0; j < 8; ++j) { scv[j] = sc[dbase + j]; biv[j] = bi[dbase + j]; }
    float* dstbase = isq ? g_Q : g_K;

    #pragma unroll
    for (int i = 0; i < 8; ++i) {
        float v[8];
        float s = 0.f, sq = 0.f;
        #pragma unroll
        for (int j = 0; j < 8; ++j) {
            v[j] = acc[i][j] * 0.03125f;       // / 1024^0.5
            s += v[j]; sq += v[j] * v[j];
        }
        // reduce over the 8 lanes covering this row's 64 dims (lane bits 0..2)
        #pragma unroll
        for (int m = 1; m < 8; m <<= 1) {
            s  += __shfl_xor_sync(0xffffffffu, s,  m);
            sq += __shfl_xor_sync(0xffffffffu, sq, m);
        }
        float mean = s * (1.f / 64.f);
        float var  = sq * (1.f / 64.f) - mean * mean;
        float inv  = rsqrtf(var + 1e-6f);
        int mg = row0 + ty * 8 + i;
        int b = mg >> 11, l = mg & (LSEQ - 1);
        float* dst = dstbase + (((size_t)(b * HEADS + h)) * LSEQ + l) * DHEAD + dbase;
        float o[8];
        #pragma unroll
        for (int j = 0; j < 8; ++j) o[j] = (v[j] - mean) * inv * scv[j] + biv[j];
        *(float4*)&dst[0] = *(float4*)&o[0];
        *(float4*)&dst[4] = *(float4*)&o[4];
    }
}

// ---------------------------------------------------------------------------
// Kernel 2: v = (X @ W_v)/32 -> g_V in [bh, l, 64]. Grid: (8 ntiles, 32 mtiles)
// ---------------------------------------------------------------------------
__global__ __launch_bounds__(256) void k_v(
    const float* __restrict__ X, const float* __restrict__ Wv)
{
    __shared__ float As[2][8][128], Bs[2][8][128];
    float acc[8][8];
    const int col0 = blockIdx.x * 128;
    const int row0 = blockIdx.y * 128;
    gemm_core(X, Wv, DMODEL, row0, col0, As, Bs, acc);

    const int tid = threadIdx.x, ty = tid >> 4, tx = tid & 15;
    const int n0 = col0 + tx * 8;
    const int h = n0 >> 6, d = n0 & 63;
    #pragma unroll
    for (int i = 0; i < 8; ++i) {
        int mg = row0 + ty * 8 + i;
        int b = mg >> 11, l = mg & (LSEQ - 1);
        float* dst = g_V + (((size_t)(b * HEADS + h)) * LSEQ + l) * DHEAD + d;
        float o[8];
        #pragma unroll
        for (int j = 0; j < 8; ++j) o[j] = acc[i][j] * 0.03125f;   // / sqrt(1024)
        *(float4*)&dst[0] = *(float4*)&o[0];
        *(float4*)&dst[4] = *(float4*)&o[4];
    }
}

// ---------------------------------------------------------------------------
// Kernel 3: causal attention per (bh, qtile). S in regs, P via smem, running
// row-sum (reference uses raw exp: no max rescale needed). Grid: (16, 32).
// smem: Qs^T[64][132] + Ks^T[64][132] + Ps[128][128] + Vs[128][64]
// ---------------------------------------------------------------------------
#define ATTN_SMEM ((2 * 64 * 132 + 128 * 128 + 128 * 64) * 4)

__global__ __launch_bounds__(256) void k_attn()
{
    extern __shared__ float sm[];
    float* Qs = sm;                       // [64][132], Qs[d*132 + i]
    float* Ks = sm + 64 * 132;            // [64][132]
    float* Ps = sm + 2 * 64 * 132;        // [128][128], row-major
    float* Vs = Ps + 128 * 128;           // [128][64]

    const int qt = blockIdx.x, bh = blockIdx.y;
    const int tid = threadIdx.x, ty = tid >> 4, tx = tid & 15;

    const float* Qg = g_Q + ((size_t)bh * LSEQ + qt * 128) * DHEAD;
    #pragma unroll
    for (int it = 0; it < 8; ++it) {
        int idx = tid + it * 256;
        int i = idx >> 4, d4 = (idx & 15) << 2;
        float4 v = *(const float4*)&Qg[i * DHEAD + d4];
        Qs[(d4 + 0) * 132 + i] = v.x;
        Qs[(d4 + 1) * 132 + i] = v.y;
        Qs[(d4 + 2) * 132 + i] = v.z;
        Qs[(d4 + 3) * 132 + i] = v.w;
    }

    float o[8][4];
    float den[8];
    #pragma unroll
    for (int r = 0; r < 8; ++r) {
        den[r] = 0.f;
        #pragma unroll
        for (int c = 0; c < 4; ++c) o[r][c] = 0.f;
    }

    #pragma unroll 1
    for (int jt = 0; jt <= qt; ++jt) {
        __syncthreads();   // prior PV done before overwriting Ks/Vs
        const float* Kg = g_K + ((size_t)bh * LSEQ + jt * 128) * DHEAD;
        const float* Vg = g_V + ((size_t)bh * LSEQ + jt * 128) * DHEAD;
        #pragma unroll
        for (int it = 0; it < 8; ++it) {
            int idx = tid + it * 256;
            int i = idx >> 4, d4 = (idx & 15) << 2;
            float4 v = *(const float4*)&Kg[i * DHEAD + d4];
            Ks[(d4 + 0) * 132 + i] = v.x;
            Ks[(d4 + 1) * 132 + i] = v.y;
            Ks[(d4 + 2) * 132 + i] = v.z;
            Ks[(d4 + 3) * 132 + i] = v.w;
            *(float4*)&Vs[i * DHEAD + d4] = *(const float4*)&Vg[i * DHEAD + d4];
        }
        __syncthreads();

        // S[128x128] = Q K^T, thread owns rows ty*8.., cols tx*8..
        float s[8][8];
        #pragma unroll
        for (int i = 0; i < 8; ++i)
            #pragma unroll
            for (int j = 0; j < 8; ++j) s[i][j] = 0.f;
        #pragma unroll 8
        for (int d = 0; d < 64; ++d) {
            float a[8], b[8];
            *(float4*)&a[0] = *(const float4*)&Qs[d * 132 + ty * 8];
            *(float4*)&a[4] = *(const float4*)&Qs[d * 132 + ty * 8 + 4];
            *(float4*)&b[0] = *(const float4*)&Ks[d * 132 + tx * 8];
            *(float4*)&b[4] = *(const float4*)&Ks[d * 132 + tx * 8 + 4];
            #pragma unroll
            for (int i = 0; i < 8; ++i)
                #pragma unroll
                for (int j = 0; j < 8; ++j)
                    s[i][j] = fmaf(a[i], b[j], s[i][j]);
        }

        // exp + causal mask + stage P + accumulate row sums
        const bool diag = (jt == qt);
        #pragma unroll
        for (int i = 0; i < 8; ++i) {
            const int rq = ty * 8 + i;
            float p[8];
            #pragma unroll
            for (int j = 0; j < 8; ++j) {
                float e = fast_exp(s[i][j] * 0.015625f);   // / 64^1
                if (diag && (tx * 8 + j > rq)) e = 0.f;
                p[j] = e;
                den[i] += e;
            }
            *(float4*)&Ps[rq * 128 + tx * 8]     = *(float4*)&p[0];
            *(float4*)&Ps[rq * 128 + tx * 8 + 4] = *(float4*)&p[4];
        }
        __syncthreads();

        // O[128x64] += P[128x128] @ V[128x64]; thread rows ty*8.., cols tx*4..
        #pragma unroll 4
        for (int kk = 0; kk < 128; ++kk) {
            float4 bv = *(const float4*)&Vs[kk * DHEAD + tx * 4];
            #pragma unroll
            for (int r = 0; r < 8; ++r) {
                float a = Ps[(ty * 8 + r) * 128 + kk];
                o[r][0] = fmaf(a, bv.x, o[r][0]);
                o[r][1] = fmaf(a, bv.y, o[r][1]);
                o[r][2] = fmaf(a, bv.z, o[r][2]);
                o[r][3] = fmaf(a, bv.w, o[r][3]);
            }
        }
    }

    // reduce den across the 16 tx lanes (lane bits 0..3), normalize, write Y
    #pragma unroll
    for (int r = 0; r < 8; ++r)
        #pragma unroll
        for (int m = 1; m < 16; m <<= 1)
            den[r] += __shfl_xor_sync(0xffffffffu, den[r], m);

    const int b = bh >> 4, h = bh & 15;
    #pragma unroll
    for (int r = 0; r < 8; ++r) {
        float inv = 1.f / den[r];
        int l = qt * 128 + ty * 8 + r;
        float4 ov = make_float4(o[r][0] * inv, o[r][1] * inv, o[r][2] * inv, o[r][3] * inv);
        *(float4*)&g_Y[((size_t)b * LSEQ + l) * DMODEL + h * DHEAD + tx * 4] = ov;
    }
}

// ---------------------------------------------------------------------------
// Kernel 4: out = (Y @ W_out)/32 -> d_out. Grid: (8, 32)
// ---------------------------------------------------------------------------
__global__ __launch_bounds__(256) void k_out(
    const float* __restrict__ Wout, float* __restrict__ Cout)
{
    __shared__ float As[2][8][128], Bs[2][8][128];
    float acc[8][8];
    const int col0 = blockIdx.x * 128;
    const int row0 = blockIdx.y * 128;
    gemm_core(g_Y, Wout, DMODEL, row0, col0, As, Bs, acc);

    const int tid = threadIdx.x, ty = tid >> 4, tx = tid & 15;
    #pragma unroll
    for (int i = 0; i < 8; ++i) {
        int mg = row0 + ty * 8 + i;
        float* dst = Cout + (size_t)mg * DMODEL + col0 + tx * 8;
        float o[8];
        #pragma unroll
        for (int j = 0; j < 8; ++j) o[j] = acc[i][j] * 0.03125f;   // / sqrt(1024)
        *(float4*)&dst[0] = *(float4*)&o[0];
        *(float4*)&dst[4] = *(float4*)&o[4];
    }
}

// ---------------------------------------------------------------------------
extern "C" void kernel_launch(void* const* d_in, const int* in_sizes, int n_in,
                              void* d_out, int out_size)
{
    const float* X    = (const float*)d_in[0];
    const float* Wqk  = (const float*)d_in[1];
    const float* Wv   = (const float*)d_in[2];
    const float* Wout = (const float*)d_in[3];
    const float* qsc  = (const float*)d_in[4];
    const float* qbi  = (const float*)d_in[5];
    const float* ksc  = (const float*)d_in[6];
    const float* kbi  = (const float*)d_in[7];
    float* out = (float*)d_out;

    cudaFuncSetAttribute(k_attn, cudaFuncAttributeMaxDynamicSharedMemorySize, ATTN_SMEM);

    dim3 blk(256);
    k_qk_ln<<<dim3(HEADS, MROWS / 128), blk>>>(X, Wqk, qsc, qbi, ksc, kbi);
    k_v<<<dim3(DMODEL / 128, MROWS / 128), blk>>>(X, Wv);
    k_attn<<<dim3(LSEQ / 128, BH), blk, ATTN_SMEM>>>();
    k_out<<<dim3(DMODEL / 128, MROWS / 128), blk>>>(Wout, out);
}

// round 8
// speedup vs baseline: 2.3730x; 2.3730x over previous
#include <cuda_runtime.h>
#include <cstdint>
#include <cstddef>

#define LSEQ   2048
#define HEADS  16
#define DHEAD  64
#define DMODEL 1024
#define MROWS  4096
#define BH     32

typedef unsigned short u16;   // bf16 bit pattern

// ---------------- scratch: exactly 64 MiB (the R1-proven footprint) --------
__device__ u16   g_Qh[BH * LSEQ * DHEAD], g_Ql[BH * LSEQ * DHEAD];   // 16 MiB
__device__ u16   g_Kh[BH * LSEQ * DHEAD], g_Kl[BH * LSEQ * DHEAD];   // 16 MiB
__device__ u16   g_Vth[BH * DHEAD * LSEQ], g_Vtl[BH * DHEAD * LSEQ]; // 16 MiB
__device__ float g_Yf[MROWS * DMODEL];                               // 16 MiB

// ---------------- helpers --------------------------------------------------
__device__ __forceinline__ uint32_t smem_u32(const void* p) {
    uint32_t a;
    asm("{ .reg .u64 t; cvta.to.shared.u64 t, %1; cvt.u32.u64 %0, t; }" : "=r"(a) : "l"(p));
    return a;
}

#define LDSM4(r0, r1, r2, r3, addr) \
    asm volatile("ldmatrix.sync.aligned.m8n8.x4.shared.b16 {%0,%1,%2,%3}, [%4];" \
        : "=r"(r0), "=r"(r1), "=r"(r2), "=r"(r3) : "r"(addr))

#define LDSM4T(r0, r1, r2, r3, addr) \
    asm volatile("ldmatrix.sync.aligned.m8n8.x4.trans.shared.b16 {%0,%1,%2,%3}, [%4];" \
        : "=r"(r0), "=r"(r1), "=r"(r2), "=r"(r3) : "r"(addr))

#define MMA4(c0, c1, c2, c3, a0, a1, a2, a3, b0, b1) \
    asm volatile("mma.sync.aligned.m16n8k16.row.col.f32.bf16.bf16.f32 " \
        "{%0,%1,%2,%3}, {%4,%5,%6,%7}, {%8,%9}, {%0,%1,%2,%3};" \
        : "+f"(c0), "+f"(c1), "+f"(c2), "+f"(c3) \
        : "r"(a0), "r"(a1), "r"(a2), "r"(a3), "r"(b0), "r"(b1))

__device__ __forceinline__ void cpasync16(uint32_t dst, const void* src) {
    asm volatile("cp.async.cg.shared.global [%0], [%1], 16;" :: "r"(dst), "l"(src));
}
#define CP_COMMIT() asm volatile("cp.async.commit_group;" ::: "memory")
#define CP_WAIT(n)  asm volatile("cp.async.wait_group %0;" :: "n"(n) : "memory")

__device__ __forceinline__ float fast_exp(float x) {
    float y = x * 1.4426950408889634f;
    float z = y + 12582912.0f;
    int   n = __float_as_int(z) - 0x4B400000;
    float f = y - (z - 12582912.0f);
    float p = 1.3333558146e-3f;
    p = fmaf(p, f, 9.6181291076e-3f);
    p = fmaf(p, f, 5.5504108665e-2f);
    p = fmaf(p, f, 2.4022650696e-1f);
    p = fmaf(p, f, 6.9314718056e-1f);
    p = fmaf(p, f, 1.0f);
    return __int_as_float(__float_as_int(p) + (n << 23));
}
__device__ __forceinline__ uint32_t pack2(float a, float b) {
    uint32_t r;
    asm("cvt.rn.bf16x2.f32 %0, %1, %2;" : "=r"(r) : "f"(b), "f"(a));
    return r;
}
__device__ __forceinline__ float bf16_rn(float v) {
    uint32_t u = __float_as_uint(v);
    return __uint_as_float((u + 0x7FFFu + ((u >> 16) & 1u)) & 0xFFFF0000u);
}
__device__ __forceinline__ void bsplit(float v, float& hi, float& lo) {
    hi = bf16_rn(v);
    lo = v - hi;
}
__device__ __forceinline__ u16 bf16_bits(float v_already_rounded) {
    return (u16)(__float_as_uint(v_already_rounded) >> 16);
}

// ===========================================================================
// Projection GEMM (macro — no arrays cross a function boundary).
// C[128x128] = split( A_f32[128x1024] ) @ split( B_f32[1024 x N] tile ),
// 3-product hi/lo split. BK = 32, register-prefetched fp32 loads, on-the-fly
// bf16 hi/lo conversion into padded smem tiles.
//   A tile: [128 m][80 B]  (64 B data + 16 pad), ldmatrix non-trans
//   B tile: [32 k][272 B]  (256 B data + 16 pad), ldmatrix.trans
// Requires in scope: cb (char* smem), tid, lane, wid, wm, wn, sb,
//                    float acc[2][8][4] (zeroed).
// ===========================================================================
#define OFF_AH 0
#define OFF_AL 10240
#define OFF_BH 20480
#define OFF_BL 29184
#define PROJ_TILE_SMEM 37888

#define CVT8_STS(dsthi, dstlo, va, vb)                                        \
    {                                                                         \
        float h0,l0,h1,l1,h2,l2,h3,l3,h4,l4,h5,l5,h6,l6,h7,l7;                \
        bsplit(va.x,h0,l0); bsplit(va.y,h1,l1); bsplit(va.z,h2,l2);           \
        bsplit(va.w,h3,l3); bsplit(vb.x,h4,l4); bsplit(vb.y,h5,l5);           \
        bsplit(vb.z,h6,l6); bsplit(vb.w,h7,l7);                               \
        uint4 uh, ul;                                                         \
        uh.x = pack2(h0,h1); uh.y = pack2(h2,h3);                             \
        uh.z = pack2(h4,h5); uh.w = pack2(h6,h7);                             \
        ul.x = pack2(l0,l1); ul.y = pack2(l2,l3);                             \
        ul.z = pack2(l4,l5); ul.w = pack2(l6,l7);                             \
        *(uint4*)(dsthi) = uh;                                                \
        *(uint4*)(dstlo) = ul;                                                \
    }

#define PROJ_GEMM_BODY(APTR, BPTR, LDB, N0)                                   \
{                                                                             \
    const int r_a = tid >> 1, kq_a = (tid & 1) * 16;                          \
    const int k_b = tid >> 3, nq_b = (tid & 7) * 16;                          \
    const float* gA = (APTR) + (size_t)r_a * DMODEL + kq_a;                   \
    const float* gB = (BPTR) + (size_t)k_b * (LDB) + (N0) + nq_b;             \
    float4 pa0 = *(const float4*)(gA + 0),  pa1 = *(const float4*)(gA + 4);   \
    float4 pa2 = *(const float4*)(gA + 8),  pa3 = *(const float4*)(gA + 12);  \
    float4 pb0 = *(const float4*)(gB + 0),  pb1 = *(const float4*)(gB + 4);   \
    float4 pb2 = *(const float4*)(gB + 8),  pb3 = *(const float4*)(gB + 12);  \
    char* aH = cb + OFF_AH + r_a * 80 + (kq_a >> 3) * 16;                     \
    char* bH = cb + OFF_BH + k_b * 272 + nq_b * 2;                            \
    _Pragma("unroll 1")                                                       \
    for (int kc = 0; kc < 32; ++kc) {                                         \
        __syncthreads();                      /* tiles free               */  \
        CVT8_STS(aH,                   aH + (OFF_AL - OFF_AH), pa0, pa1);     \
        CVT8_STS(aH + 16,              aH + (OFF_AL - OFF_AH) + 16, pa2, pa3);\
        CVT8_STS(bH,                   bH + (OFF_BL - OFF_BH), pb0, pb1);     \
        CVT8_STS(bH + 16,              bH + (OFF_BL - OFF_BH) + 16, pb2, pb3);\
        __syncthreads();                      /* tiles ready              */  \
        if (kc < 31) {                                                        \
            gA += 32;  gB += (size_t)32 * (LDB);                              \
            pa0 = *(const float4*)(gA + 0);  pa1 = *(const float4*)(gA + 4);  \
            pa2 = *(const float4*)(gA + 8);  pa3 = *(const float4*)(gA + 12); \
            pb0 = *(const float4*)(gB + 0);  pb1 = *(const float4*)(gB + 4);  \
            pb2 = *(const float4*)(gB + 8);  pb3 = *(const float4*)(gB + 12); \
        }                                                                     \
        _Pragma("unroll")                                                     \
        for (int ks = 0; ks < 2; ++ks) {                                      \
            uint32_t ah[2][4], al[2][4];                                      \
            _Pragma("unroll")                                                 \
            for (int i = 0; i < 2; ++i) {                                     \
                int row = wm * 32 + i * 16 + (lane & 15);                     \
                uint32_t a = sb + OFF_AH + row * 80                           \
                           + (ks * 2 + (lane >> 4)) * 16;                     \
                LDSM4(ah[i][0], ah[i][1], ah[i][2], ah[i][3], a);             \
                LDSM4(al[i][0], al[i][1], al[i][2], al[i][3],                 \
                      a + (OFF_AL - OFF_AH));                                 \
            }                                                                 \
            _Pragma("unroll")                                                 \
            for (int np = 0; np < 4; ++np) {                                  \
                int tilei = lane >> 3;                                        \
                int krow = ks * 16 + (tilei & 1) * 8 + (lane & 7);            \
                int ncol = wn * 64 + np * 16 + (tilei >> 1) * 8;              \
                uint32_t a = sb + OFF_BH + krow * 272 + ncol * 2;             \
                uint32_t b0, b1, b2, b3, c0, c1, c2, c3;                      \
                LDSM4T(b0, b1, b2, b3, a);                                    \
                LDSM4T(c0, c1, c2, c3, a + (OFF_BL - OFF_BH));                \
                _Pragma("unroll")                                             \
                for (int i = 0; i < 2; ++i) {                                 \
                    MMA4(acc[i][2*np][0], acc[i][2*np][1],                    \
                         acc[i][2*np][2], acc[i][2*np][3],                    \
                         ah[i][0], ah[i][1], ah[i][2], ah[i][3], b0, b1);     \
                    MMA4(acc[i][2*np][0], acc[i][2*np][1],                    \
                         acc[i][2*np][2], acc[i][2*np][3],                    \
                         al[i][0], al[i][1], al[i][2], al[i][3], b0, b1);     \
                    MMA4(acc[i][2*np][0], acc[i][2*np][1],                    \
                         acc[i][2*np][2], acc[i][2*np][3],                    \
                         ah[i][0], ah[i][1], ah[i][2], ah[i][3], c0, c1);     \
                    MMA4(acc[i][2*np+1][0], acc[i][2*np+1][1],                \
                         acc[i][2*np+1][2], acc[i][2*np+1][3],                \
                         ah[i][0], ah[i][1], ah[i][2], ah[i][3], b2, b3);     \
                    MMA4(acc[i][2*np+1][0], acc[i][2*np+1][1],                \
                         acc[i][2*np+1][2], acc[i][2*np+1][3],                \
                         al[i][0], al[i][1], al[i][2], al[i][3], b2, b3);     \
                    MMA4(acc[i][2*np+1][0], acc[i][2*np+1][1],                \
                         acc[i][2*np+1][2], acc[i][2*np+1][3],                \
                         ah[i][0], ah[i][1], ah[i][2], ah[i][3], c2, c3);     \
                }                                                             \
            }                                                                 \
        }                                                                     \
    }                                                                         \
}

#define PROJ_PROLOGUE()                                                       \
    extern __shared__ char cb[];                                              \
    const uint32_t sb = smem_u32(cb);                                         \
    const int tid = threadIdx.x, lane = tid & 31, wid = tid >> 5;             \
    const int wm = wid & 3, wn = wid >> 2;                                    \
    float acc[2][8][4];                                                       \
    _Pragma("unroll")                                                         \
    for (int i = 0; i < 2; ++i)                                               \
        _Pragma("unroll")                                                     \
        for (int j = 0; j < 8; ++j)                                           \
            _Pragma("unroll")                                                 \
            for (int c = 0; c < 4; ++c) acc[i][j][c] = 0.f;

// ---------------------------------------------------------------------------
// QK projection + per-head LayerNorm. grid (16 heads, 32 mtiles)
// ---------------------------------------------------------------------------
__global__ __launch_bounds__(256, 1) void k_qk_ln(
    const float* __restrict__ X, const float* __restrict__ Wqk,
    const float* __restrict__ qsc, const float* __restrict__ qbi,
    const float* __restrict__ ksc, const float* __restrict__ kbi)
{
    PROJ_PROLOGUE();
    const int h = blockIdx.x, row0 = blockIdx.y * 128;
    PROJ_GEMM_BODY(X + (size_t)row0 * DMODEL, Wqk, 2048, h * 128);

    const int g = lane >> 2, tg = lane & 3;
    const float* sc = wn ? ksc : qsc;
    const float* bi = wn ? kbi : qbi;
    u16* dh = wn ? g_Kh : g_Qh;
    u16* dl = wn ? g_Kl : g_Ql;

    #pragma unroll
    for (int i = 0; i < 2; ++i) {
        float s0 = 0.f, s1 = 0.f, q0 = 0.f, q1 = 0.f;
        #pragma unroll
        for (int j = 0; j < 8; ++j) {
            #pragma unroll
            for (int c = 0; c < 4; ++c) acc[i][j][c] *= 0.03125f;
            s0 += acc[i][j][0] + acc[i][j][1];
            s1 += acc[i][j][2] + acc[i][j][3];
            q0 += acc[i][j][0] * acc[i][j][0] + acc[i][j][1] * acc[i][j][1];
            q1 += acc[i][j][2] * acc[i][j][2] + acc[i][j][3] * acc[i][j][3];
        }
        #pragma unroll
        for (int m = 1; m < 4; m <<= 1) {
            s0 += __shfl_xor_sync(0xffffffffu, s0, m);
            s1 += __shfl_xor_sync(0xffffffffu, s1, m);
            q0 += __shfl_xor_sync(0xffffffffu, q0, m);
            q1 += __shfl_xor_sync(0xffffffffu, q1, m);
        }
        float mu0 = s0 * (1.f / 64.f), mu1 = s1 * (1.f / 64.f);
        float iv0 = rsqrtf(q0 * (1.f / 64.f) - mu0 * mu0 + 1e-6f);
        float iv1 = rsqrtf(q1 * (1.f / 64.f) - mu1 * mu1 + 1e-6f);

        int m = row0 + wm * 32 + i * 16 + g;
        int b = m >> 11, l = m & (LSEQ - 1);
        size_t base0 = ((size_t)(b * HEADS + h) * LSEQ + l) * DHEAD;
        size_t base1 = base0 + 8 * DHEAD;

        #pragma unroll
        for (int j = 0; j < 8; ++j) {
            int col = j * 8 + 2 * tg;
            float sc0 = sc[col], sc1 = sc[col + 1], bi0 = bi[col], bi1 = bi[col + 1];
            float y0 = (acc[i][j][0] - mu0) * iv0 * sc0 + bi0;
            float y1 = (acc[i][j][1] - mu0) * iv0 * sc1 + bi1;
            float y2 = (acc[i][j][2] - mu1) * iv1 * sc0 + bi0;
            float y3 = (acc[i][j][3] - mu1) * iv1 * sc1 + bi1;
            float h0, l0, h1, l1, h2, l2, h3, l3;
            bsplit(y0, h0, l0); bsplit(y1, h1, l1); bsplit(y2, h2, l2); bsplit(y3, h3, l3);
            *(uint32_t*)(dh + base0 + col) = pack2(h0, h1);
            *(uint32_t*)(dl + base0 + col) = pack2(l0, l1);
            *(uint32_t*)(dh + base1 + col) = pack2(h2, h3);
            *(uint32_t*)(dl + base1 + col) = pack2(l2, l3);
        }
    }
}

// ---------------------------------------------------------------------------
// V projection -> transposed Vt [bh][d][l] (smem transpose). grid (8, 32)
// ---------------------------------------------------------------------------
#define KV_SMEM 69632

__global__ __launch_bounds__(256, 1) void k_v(
    const float* __restrict__ X, const float* __restrict__ Wv)
{
    PROJ_PROLOGUE();
    const int n0b = blockIdx.x * 128, row0 = blockIdx.y * 128;
    PROJ_GEMM_BODY(X + (size_t)row0 * DMODEL, Wv, 1024, n0b);

    u16* Th = (u16*)cb;                 // [128 n][136 m]
    u16* Tl = (u16*)(cb + 34816);
    const int g = lane >> 2, tg = lane & 3;
    __syncthreads();

    #pragma unroll
    for (int i = 0; i < 2; ++i) {
        int r0 = wm * 32 + i * 16 + g;
        #pragma unroll
        for (int j = 0; j < 8; ++j) {
            int n = wn * 64 + j * 8 + 2 * tg;
            float h0, l0, h1, l1, h2, l2, h3, l3;
            bsplit(acc[i][j][0] * 0.03125f, h0, l0);
            bsplit(acc[i][j][1] * 0.03125f, h1, l1);
            bsplit(acc[i][j][2] * 0.03125f, h2, l2);
            bsplit(acc[i][j][3] * 0.03125f, h3, l3);
            Th[n * 136 + r0]           = bf16_bits(h0);
            Th[(n + 1) * 136 + r0]     = bf16_bits(h1);
            Th[n * 136 + r0 + 8]       = bf16_bits(h2);
            Th[(n + 1) * 136 + r0 + 8] = bf16_bits(h3);
            Tl[n * 136 + r0]           = bf16_bits(bf16_rn(l0));
            Tl[(n + 1) * 136 + r0]     = bf16_bits(bf16_rn(l1));
            Tl[n * 136 + r0 + 8]       = bf16_bits(bf16_rn(l2));
            Tl[(n + 1) * 136 + r0 + 8] = bf16_bits(bf16_rn(l3));
        }
    }
    __syncthreads();

    const int n = tid >> 1, mh = (tid & 1) * 64;
    const int ng = n0b + n, hh = ng >> 6, d = ng & 63;
    const int b = row0 >> 11, l0 = row0 & (LSEQ - 1);
    u16* dsth = g_Vth + ((size_t)(b * HEADS + hh) * DHEAD + d) * LSEQ + l0 + mh;
    u16* dstl = g_Vtl + ((size_t)(b * HEADS + hh) * DHEAD + d) * LSEQ + l0 + mh;
    #pragma unroll
    for (int u = 0; u < 8; ++u) {
        *(uint4*)(dsth + u * 8) = *(uint4*)(Th + n * 136 + mh + u * 8);
        *(uint4*)(dstl + u * 8) = *(uint4*)(Tl + n * 136 + mh + u * 8);
    }
}

// ---------------------------------------------------------------------------
// out projection -> d_out fp32. grid (8, 32)
// ---------------------------------------------------------------------------
__global__ __launch_bounds__(256, 1) void k_out(
    const float* __restrict__ Wout, float* __restrict__ out)
{
    PROJ_PROLOGUE();
    const int col0 = blockIdx.x * 128, row0 = blockIdx.y * 128;
    PROJ_GEMM_BODY(g_Yf + (size_t)row0 * DMODEL, Wout, 1024, col0);

    const int g = lane >> 2, tg = lane & 3;
    #pragma unroll
    for (int i = 0; i < 2; ++i) {
        int r = row0 + wm * 32 + i * 16 + g;
        #pragma unroll
        for (int j = 0; j < 8; ++j) {
            int c = col0 + wn * 64 + j * 8 + 2 * tg;
            float2 v0 = make_float2(acc[i][j][0] * 0.03125f, acc[i][j][1] * 0.03125f);
            float2 v1 = make_float2(acc[i][j][2] * 0.03125f, acc[i][j][3] * 0.03125f);
            *(float2*)(out + (size_t)r * DMODEL + c) = v0;
            *(float2*)(out + (size_t)(r + 8) * DMODEL + c) = v1;
        }
    }
}

// ---------------------------------------------------------------------------
// attention. grid (16 qt, 32 bh), 256 threads, warp w owns q-rows 16w..16w+15.
// Fused S->P->PV per 16-column chunk. smem 160 KB. Output Y is fp32.
// ---------------------------------------------------------------------------
#define ATTN_SMEM 163840

__device__ __forceinline__ void attn_load_kv(uint32_t sbuf, int bh, int jt, int tid)
{
    {
        const int r = tid >> 1, cbx = (tid & 1) * 4;
        const size_t go = ((size_t)bh * LSEQ + jt * 128 + r) * DHEAD + cbx * 8;
        const uint32_t base = sbuf + r * 128;
        #pragma unroll
        for (int c = 0; c < 4; ++c) {
            uint32_t cc = ((uint32_t)(cbx + c) ^ (r & 7)) * 16;
            cpasync16(base + cc,         g_Kh + go + c * 8);
            cpasync16(base + 16384 + cc, g_Kl + go + c * 8);
        }
    }
    {
        const int r = tid >> 2, cbx = (tid & 3) * 4;
        const size_t go = ((size_t)bh * DHEAD + r) * LSEQ + jt * 128 + cbx * 8;
        const uint32_t base = sbuf + 32768 + r * 256;
        #pragma unroll
        for (int c = 0; c < 4; ++c) {
            uint32_t cc = ((uint32_t)(cbx + c) ^ ((r & 7) << 1)) * 16;
            cpasync16(base + cc,         g_Vth + go + c * 8);
            cpasync16(base + 16384 + cc, g_Vtl + go + c * 8);
        }
    }
    CP_COMMIT();
}

__global__ __launch_bounds__(256, 1) void k_attn()
{
    extern __shared__ char smraw[];
    const uint32_t sb = smem_u32(smraw);
    const int qt = (int)gridDim.x - 1 - (int)blockIdx.x;   // big tiles first
    const int bh = blockIdx.y;
    const int tid = threadIdx.x, lane = tid & 31, wid = tid >> 5;
    const int g = lane >> 2, tg = lane & 3;

    // stage Q (group 1)
    {
        const int r = tid >> 1, cbx = (tid & 1) * 4;
        const size_t go = ((size_t)bh * LSEQ + qt * 128 + r) * DHEAD + cbx * 8;
        const uint32_t base = sb + r * 128;
        #pragma unroll
        for (int c = 0; c < 4; ++c) {
            uint32_t cc = ((uint32_t)(cbx + c) ^ (r & 7)) * 16;
            cpasync16(base + cc,         g_Qh + go + c * 8);
            cpasync16(base + 16384 + cc, g_Ql + go + c * 8);
        }
        CP_COMMIT();
    }
    attn_load_kv(sb + 32768, bh, 0, tid);   // group 2 (KV jt=0)

    CP_WAIT(1);        // Q arrived (KV0 may still be in flight)
    __syncthreads();

    // Q fragments (register-resident for whole kernel)
    uint32_t qh[4][4], ql[4][4];
    {
        int row = wid * 16 + (lane & 15);
        #pragma unroll
        for (int l = 0; l < 4; ++l) {
            int chunk = 2 * l + (lane >> 4);
            uint32_t a = sb + row * 128 + ((chunk ^ (row & 7)) * 16);
            LDSM4(qh[l][0], qh[l][1], qh[l][2], qh[l][3], a);
            LDSM4(ql[l][0], ql[l][1], ql[l][2], ql[l][3], a + 16384);
        }
    }

    float o[8][4];
    #pragma unroll
    for (int j = 0; j < 8; ++j)
        #pragma unroll
        for (int c = 0; c < 4; ++c) o[j][c] = 0.f;
    float den0 = 0.f, den1 = 0.f;

    const int rq = wid * 16 + g;

    int buf = 0;
    #pragma unroll 1
    for (int jt = 0; jt <= qt; ++jt) {
        if (jt < qt) { attn_load_kv(sb + 32768 + (buf ^ 1) * 65536, bh, jt + 1, tid); CP_WAIT(1); }
        else CP_WAIT(0);
        __syncthreads();
        const uint32_t sK = sb + 32768 + buf * 65536;
        const uint32_t sV = sK + 32768;

        const bool dg = (jt == qt);
        const int kkmax = dg ? wid : 7;

        #pragma unroll 1
        for (int kk = 0; kk <= kkmax; ++kk) {
            // ---- S chunk: 16 q-rows x 16 k-cols (hh + lh + hl) ----
            float s0[4] = {0.f, 0.f, 0.f, 0.f};
            float s1[4] = {0.f, 0.f, 0.f, 0.f};
            {
                int row = kk * 16 + (lane & 7) + ((lane >> 4) << 3);
                #pragma unroll
                for (int l = 0; l < 4; ++l) {
                    int chunk = 2 * l + ((lane >> 3) & 1);
                    uint32_t a = sK + row * 128 + ((chunk ^ (row & 7)) * 16);
                    uint32_t b0, b1, b2, b3, c0, c1, c2, c3;
                    LDSM4(b0, b1, b2, b3, a);
                    LDSM4(c0, c1, c2, c3, a + 16384);
                    MMA4(s0[0], s0[1], s0[2], s0[3], qh[l][0], qh[l][1], qh[l][2], qh[l][3], b0, b1);
                    MMA4(s0[0], s0[1], s0[2], s0[3], ql[l][0], ql[l][1], ql[l][2], ql[l][3], b0, b1);
                    MMA4(s0[0], s0[1], s0[2], s0[3], qh[l][0], qh[l][1], qh[l][2], qh[l][3], c0, c1);
                    MMA4(s1[0], s1[1], s1[2], s1[3], qh[l][0], qh[l][1], qh[l][2], qh[l][3], b2, b3);
                    MMA4(s1[0], s1[1], s1[2], s1[3], ql[l][0], ql[l][1], ql[l][2], ql[l][3], b2, b3);
                    MMA4(s1[0], s1[1], s1[2], s1[3], qh[l][0], qh[l][1], qh[l][2], qh[l][3], c2, c3);
                }
            }

            // ---- exp + causal mask + den + split into P A-fragment ----
            uint32_t p0, p1, p2, p3, r0, r1, r2, r3;
            {
                float e0 = fast_exp(s0[0] * 0.015625f);
                float e1 = fast_exp(s0[1] * 0.015625f);
                float e2 = fast_exp(s0[2] * 0.015625f);
                float e3 = fast_exp(s0[3] * 0.015625f);
                float f0 = fast_exp(s1[0] * 0.015625f);
                float f1 = fast_exp(s1[1] * 0.015625f);
                float f2 = fast_exp(s1[2] * 0.015625f);
                float f3 = fast_exp(s1[3] * 0.015625f);
                if (dg) {
                    int c0i = kk * 16 + 2 * tg;
                    if (c0i > rq)          e0 = 0.f;
                    if (c0i + 1 > rq)      e1 = 0.f;
                    if (c0i > rq + 8)      e2 = 0.f;
                    if (c0i + 1 > rq + 8)  e3 = 0.f;
                    if (c0i + 8 > rq)      f0 = 0.f;
                    if (c0i + 9 > rq)      f1 = 0.f;
                    if (c0i + 8 > rq + 8)  f2 = 0.f;
                    if (c0i + 9 > rq + 8)  f3 = 0.f;
                }
                den0 += e0 + e1 + f0 + f1;
                den1 += e2 + e3 + f2 + f3;
                float h0, l0, h1, l1;
                bsplit(e0, h0, l0); bsplit(e1, h1, l1);
                p0 = pack2(h0, h1); r0 = pack2(l0, l1);
                bsplit(e2, h0, l0); bsplit(e3, h1, l1);
                p1 = pack2(h0, h1); r1 = pack2(l0, l1);
                bsplit(f0, h0, l0); bsplit(f1, h1, l1);
                p2 = pack2(h0, h1); r2 = pack2(l0, l1);
                bsplit(f2, h0, l0); bsplit(f3, h1, l1);
                p3 = pack2(h0, h1); r3 = pack2(l0, l1);
            }

            // ---- O += P_chunk @ V_chunk ----
            {
                int row = (lane & 7) + ((lane >> 4) << 3);
                int chunk = 2 * kk + ((lane >> 3) & 1);
                #pragma unroll
                for (int np = 0; np < 4; ++np) {
                    int r2i = np * 16 + row;
                    uint32_t a = sV + r2i * 256 + ((chunk ^ ((r2i & 7) << 1)) * 16);
                    uint32_t vb0, vb1, vb2, vb3, vc0, vc1, vc2, vc3;
                    LDSM4(vb0, vb1, vb2, vb3, a);
                    LDSM4(vc0, vc1, vc2, vc3, a + 16384);
                    MMA4(o[2*np][0], o[2*np][1], o[2*np][2], o[2*np][3], p0, p1, p2, p3, vb0, vb1);
                    MMA4(o[2*np][0], o[2*np][1], o[2*np][2], o[2*np][3], r0, r1, r2, r3, vb0, vb1);
                    MMA4(o[2*np][0], o[2*np][1], o[2*np][2], o[2*np][3], p0, p1, p2, p3, vc0, vc1);
                    MMA4(o[2*np+1][0], o[2*np+1][1], o[2*np+1][2], o[2*np+1][3], p0, p1, p2, p3, vb2, vb3);
                    MMA4(o[2*np+1][0], o[2*np+1][1], o[2*np+1][2], o[2*np+1][3], r0, r1, r2, r3, vb2, vb3);
                    MMA4(o[2*np+1][0], o[2*np+1][1], o[2*np+1][2], o[2*np+1][3], p0, p1, p2, p3, vc2, vc3);
                }
            }
        }
        __syncthreads();
        buf ^= 1;
    }

    #pragma unroll
    for (int m = 1; m < 4; m <<= 1) {
        den0 += __shfl_xor_sync(0xffffffffu, den0, m);
        den1 += __shfl_xor_sync(0xffffffffu, den1, m);
    }
    const float inv0 = 1.f / den0, inv1 = 1.f / den1;

    const int b = bh >> 4, h = bh & 15;
    const size_t m0 = (size_t)b * LSEQ + qt * 128 + wid * 16 + g;
    #pragma unroll
    for (int j = 0; j < 8; ++j) {
        int d = j * 8 + 2 * tg;
        float2 v0 = make_float2(o[j][0] * inv0, o[j][1] * inv0);
        float2 v1 = make_float2(o[j][2] * inv1, o[j][3] * inv1);
        *(float2*)(g_Yf + m0 * DMODEL + h * 64 + d) = v0;
        *(float2*)(g_Yf + (m0 + 8) * DMODEL + h * 64 + d) = v1;
    }
}

// ---------------------------------------------------------------------------
extern "C" void kernel_launch(void* const* d_in, const int* in_sizes, int n_in,
                              void* d_out, int out_size)
{
    const float* X    = (const float*)d_in[0];
    const float* Wqk  = (const float*)d_in[1];
    const float* Wv   = (const float*)d_in[2];
    const float* Wout = (const float*)d_in[3];
    const float* qsc  = (const float*)d_in[4];
    const float* qbi  = (const float*)d_in[5];
    const float* ksc  = (const float*)d_in[6];
    const float* kbi  = (const float*)d_in[7];
    float* out = (float*)d_out;

    cudaFuncSetAttribute(k_v,    cudaFuncAttributeMaxDynamicSharedMemorySize, KV_SMEM);
    cudaFuncSetAttribute(k_attn, cudaFuncAttributeMaxDynamicSharedMemorySize, ATTN_SMEM);

    k_qk_ln<<<dim3(HEADS, MROWS / 128), 256, PROJ_TILE_SMEM>>>(X, Wqk, qsc, qbi, ksc, kbi);
    k_v<<<dim3(8, MROWS / 128), 256, KV_SMEM>>>(X, Wv);
    k_attn<<<dim3(LSEQ / 128, BH), 256, ATTN_SMEM>>>();
    k_out<<<dim3(8, MROWS / 128), 256, PROJ_TILE_SMEM>>>(Wout, out);
}

// round 10
// speedup vs baseline: 2.3896x; 1.0070x over previous
#include <cuda_runtime.h>
#include <cstdint>
#include <cstddef>

#define LSEQ   2048
#define HEADS  16
#define DHEAD  64
#define DMODEL 1024
#define MROWS  4096
#define BH     32

typedef unsigned short u16;   // bf16 bit pattern

// ---------------- 64 MiB aliased pool (empirical cap: 64 MiB passes, 96 trips)
// [0,24M)  elems: Qh Ql Kh Kl Vth Vtl (4M each)      — proj -> attention
// [0,2M)   elems: WOh WOl (1M each)                  — written AFTER attention
// [24,28M) elems: WQKh WQKl (2M each)  -> later Yh (4M)
// [28,30M) elems: WVh WVl (1M each)    -> later (Yl spans [28,32M))
#define POOL_ELEMS (32u * 1024u * 1024u)
__device__ __align__(256) u16 g_pool[POOL_ELEMS];

#define O_QH   (0ul)
#define O_QL   (4ul  << 20)
#define O_KH   (8ul  << 20)
#define O_KL   (12ul << 20)
#define O_VTH  (16ul << 20)
#define O_VTL  (20ul << 20)
#define O_WQKH (24ul << 20)
#define O_WQKL (26ul << 20)
#define O_WVH  (28ul << 20)
#define O_WVL  (29ul << 20)
#define O_YH   (24ul << 20)
#define O_YL   (28ul << 20)
#define O_WOH  (0ul)
#define O_WOL  (1ul << 20)

// ---------------- helpers --------------------------------------------------
__device__ __forceinline__ uint32_t smem_u32(const void* p) {
    uint32_t a;
    asm("{ .reg .u64 t; cvta.to.shared.u64 t, %1; cvt.u32.u64 %0, t; }" : "=r"(a) : "l"(p));
    return a;
}

#define LDSM4(r0, r1, r2, r3, addr) \
    asm volatile("ldmatrix.sync.aligned.m8n8.x4.shared.b16 {%0,%1,%2,%3}, [%4];" \
        : "=r"(r0), "=r"(r1), "=r"(r2), "=r"(r3) : "r"(addr))

#define LDSM4T(r0, r1, r2, r3, addr) \
    asm volatile("ldmatrix.sync.aligned.m8n8.x4.trans.shared.b16 {%0,%1,%2,%3}, [%4];" \
        : "=r"(r0), "=r"(r1), "=r"(r2), "=r"(r3) : "r"(addr))

#define MMA4(c0, c1, c2, c3, a0, a1, a2, a3, b0, b1) \
    asm volatile("mma.sync.aligned.m16n8k16.row.col.f32.bf16.bf16.f32 " \
        "{%0,%1,%2,%3}, {%4,%5,%6,%7}, {%8,%9}, {%0,%1,%2,%3};" \
        : "+f"(c0), "+f"(c1), "+f"(c2), "+f"(c3) \
        : "r"(a0), "r"(a1), "r"(a2), "r"(a3), "r"(b0), "r"(b1))

__device__ __forceinline__ void cpasync16(uint32_t dst, const void* src) {
    asm volatile("cp.async.cg.shared.global [%0], [%1], 16;" :: "r"(dst), "l"(src));
}
#define CP_COMMIT() asm volatile("cp.async.commit_group;" ::: "memory")
#define CP_WAIT(n)  asm volatile("cp.async.wait_group %0;" :: "n"(n) : "memory")

__device__ __forceinline__ float fast_exp(float x) {
    float y = x * 1.4426950408889634f;
    float z = y + 12582912.0f;
    int   n = __float_as_int(z) - 0x4B400000;
    float f = y - (z - 12582912.0f);
    float p = 1.3333558146e-3f;
    p = fmaf(p, f, 9.6181291076e-3f);
    p = fmaf(p, f, 5.5504108665e-2f);
    p = fmaf(p, f, 2.4022650696e-1f);
    p = fmaf(p, f, 6.9314718056e-1f);
    p = fmaf(p, f, 1.0f);
    return __int_as_float(__float_as_int(p) + (n << 23));
}
__device__ __forceinline__ uint32_t pack2(float a, float b) {
    uint32_t r;
    asm("cvt.rn.bf16x2.f32 %0, %1, %2;" : "=r"(r) : "f"(b), "f"(a));
    return r;
}
__device__ __forceinline__ float bf16_rn(float v) {
    uint32_t u = __float_as_uint(v);
    return __uint_as_float((u + 0x7FFFu + ((u >> 16) & 1u)) & 0xFFFF0000u);
}
__device__ __forceinline__ void bsplit(float v, float& hi, float& lo) {
    hi = bf16_rn(v);
    lo = v - hi;
}
__device__ __forceinline__ u16 bf16_bits(float v_already_rounded) {
    return (u16)(__float_as_uint(v_already_rounded) >> 16);
}

// ---------------------------------------------------------------------------
// weight splitter: fp32 [n] -> hi/lo bf16 at pool offsets
// ---------------------------------------------------------------------------
__global__ void k_wsplit(const float* __restrict__ s, size_t offh, size_t offl, int n4)
{
    int i = blockIdx.x * blockDim.x + threadIdx.x;
    if (i >= n4) return;
    float4 v = ((const float4*)s)[i];
    float h0, l0, h1, l1, h2, l2, h3, l3;
    bsplit(v.x, h0, l0); bsplit(v.y, h1, l1); bsplit(v.z, h2, l2); bsplit(v.w, h3, l3);
    uint2 uh, ul;
    uh.x = pack2(h0, h1); uh.y = pack2(h2, h3);
    ul.x = pack2(l0, l1); ul.y = pack2(l2, l3);
    ((uint2*)(g_pool + offh))[i] = uh;
    ((uint2*)(g_pool + offl))[i] = ul;
}

// ===========================================================================
// smem layouts
//   qk/v : A tile (single buf): hi[128x80B] @0, lo @10240
//          B bufs (double):     @20480, stride 17408 (hi 8704 + lo 8704)
//   out  : A bufs (double):     @0, stride 20480 (hi 10240 + lo 10240)
//          B bufs (double):     @40960, stride 17408
// ===========================================================================
#define OFF_AL   10240
#define OFF_B    20480
#define BSTRIDE  17408
#define BLO      8704
#define PROJ_SMEM 55296
#define KV_SMEM   69632          /* k_v transpose scratch needs 128*136*2*2 */
#define OUT_ABASE 0
#define OUT_ASTR  20480
#define OUT_ALO   10240
#define OUT_BBASE 40960
#define KOUT_SMEM 75776

#define CVT8_STS(dsthi, dstlo, va, vb)                                        \
    {                                                                         \
        float h0,l0,h1,l1,h2,l2,h3,l3,h4,l4,h5,l5,h6,l6,h7,l7;                \
        bsplit(va.x,h0,l0); bsplit(va.y,h1,l1); bsplit(va.z,h2,l2);           \
        bsplit(va.w,h3,l3); bsplit(vb.x,h4,l4); bsplit(vb.y,h5,l5);           \
        bsplit(vb.z,h6,l6); bsplit(vb.w,h7,l7);                               \
        uint4 uh, ul;                                                         \
        uh.x = pack2(h0,h1); uh.y = pack2(h2,h3);                             \
        uh.z = pack2(h4,h5); uh.w = pack2(h6,h7);                             \
        ul.x = pack2(l0,l1); ul.y = pack2(l2,l3);                             \
        ul.z = pack2(l4,l5); ul.w = pack2(l6,l7);                             \
        *(uint4*)(dsthi) = uh;                                                \
        *(uint4*)(dstlo) = ul;                                                \
    }

// issue one B chunk (hi+lo) for chunk index KCN into buffer base DB (smem u32)
#define CPB(KCN, DB)                                                          \
    {                                                                         \
        const u16* _sh = srcBH + (size_t)(KCN) * 32 * LDBv;                   \
        const u16* _sl = srcBL + (size_t)(KCN) * 32 * LDBv;                   \
        cpasync16((DB), _sh);            cpasync16((DB) + 16, _sh + 8);       \
        cpasync16((DB) + BLO, _sl);      cpasync16((DB) + BLO + 16, _sl + 8); \
    }

// MMA phase shared by all projections. AB0 = smem base of A-hi tile,
// ALO = byte offset A-lo, BB = smem base of B buffer (hi), lo at +BLO.
#define PROJ_MMA_PHASE(AB0, ALO2, BB)                                         \
    _Pragma("unroll")                                                         \
    for (int ks = 0; ks < 2; ++ks) {                                          \
        uint32_t ah[2][4], al[2][4];                                          \
        _Pragma("unroll")                                                     \
        for (int i = 0; i < 2; ++i) {                                         \
            int row = wm * 32 + i * 16 + (lane & 15);                         \
            uint32_t a = (AB0) + row * 80 + (ks * 2 + (lane >> 4)) * 16;      \
            LDSM4(ah[i][0], ah[i][1], ah[i][2], ah[i][3], a);                 \
            LDSM4(al[i][0], al[i][1], al[i][2], al[i][3], a + (ALO2));        \
        }                                                                     \
        _Pragma("unroll")                                                     \
        for (int np = 0; np < 4; ++np) {                                      \
            int tilei = lane >> 3;                                            \
            int krow = ks * 16 + (tilei & 1) * 8 + (lane & 7);                \
            int ncol = wn * 64 + np * 16 + (tilei >> 1) * 8;                  \
            uint32_t a = (BB) + krow * 272 + ncol * 2;                        \
            uint32_t b0, b1, b2, b3, c0, c1, c2, c3;                          \
            LDSM4T(b0, b1, b2, b3, a);                                        \
            LDSM4T(c0, c1, c2, c3, a + BLO);                                  \
            _Pragma("unroll")                                                 \
            for (int i = 0; i < 2; ++i) {                                     \
                MMA4(acc[i][2*np][0], acc[i][2*np][1],                        \
                     acc[i][2*np][2], acc[i][2*np][3],                        \
                     ah[i][0], ah[i][1], ah[i][2], ah[i][3], b0, b1);         \
                MMA4(acc[i][2*np][0], acc[i][2*np][1],                        \
                     acc[i][2*np][2], acc[i][2*np][3],                        \
                     al[i][0], al[i][1], al[i][2], al[i][3], b0, b1);         \
                MMA4(acc[i][2*np][0], acc[i][2*np][1],                        \
                     acc[i][2*np][2], acc[i][2*np][3],                        \
                     ah[i][0], ah[i][1], ah[i][2], ah[i][3], c0, c1);         \
                MMA4(acc[i][2*np+1][0], acc[i][2*np+1][1],                    \
                     acc[i][2*np+1][2], acc[i][2*np+1][3],                    \
                     ah[i][0], ah[i][1], ah[i][2], ah[i][3], b2, b3);         \
                MMA4(acc[i][2*np+1][0], acc[i][2*np+1][1],                    \
                     acc[i][2*np+1][2], acc[i][2*np+1][3],                    \
                     al[i][0], al[i][1], al[i][2], al[i][3], b2, b3);         \
                MMA4(acc[i][2*np+1][0], acc[i][2*np+1][1],                    \
                     acc[i][2*np+1][2], acc[i][2*np+1][3],                    \
                     ah[i][0], ah[i][1], ah[i][2], ah[i][3], c2, c3);         \
            }                                                                 \
        }                                                                     \
    }

// Projection with fp32 A (in-kernel split) + pre-split B via cp.async.
#define PROJ_BODY_AF32(APTR, WHOFF, WLOFF, LDB, N0)                           \
{                                                                             \
    const int r_a = tid >> 1, kq_a = (tid & 1) * 16;                          \
    const int kb = tid >> 3, nq = tid & 7;                                    \
    const int LDBv = (LDB);                                                   \
    const float* gA = (APTR) + (size_t)r_a * DMODEL + kq_a;                   \
    const u16* srcBH = g_pool + (WHOFF) + (size_t)kb * LDBv + (N0) + nq * 16; \
    const u16* srcBL = g_pool + (WLOFF) + (size_t)kb * LDBv + (N0) + nq * 16; \
    float4 pa0 = *(const float4*)(gA + 0),  pa1 = *(const float4*)(gA + 4);   \
    float4 pa2 = *(const float4*)(gA + 8),  pa3 = *(const float4*)(gA + 12);  \
    char* aH = cb + r_a * 80 + (kq_a >> 3) * 16;                              \
    const uint32_t dB = sb + OFF_B + kb * 272 + nq * 32;                      \
    CPB(0, dB);            CP_COMMIT();                                       \
    CPB(1, dB + BSTRIDE);  CP_COMMIT();                                       \
    _Pragma("unroll 1")                                                       \
    for (int kc = 0; kc < 32; ++kc) {                                         \
        __syncthreads();                                                      \
        if (kc >= 1 && kc < 31) {                                             \
            CPB(kc + 1, dB + ((kc + 1) & 1) * BSTRIDE);  CP_COMMIT();         \
        }                                                                     \
        CVT8_STS(aH,      aH + OFF_AL,      pa0, pa1);                        \
        CVT8_STS(aH + 16, aH + OFF_AL + 16, pa2, pa3);                        \
        if (kc < 31) {                                                        \
            gA += 32;                                                         \
            pa0 = *(const float4*)(gA + 0);  pa1 = *(const float4*)(gA + 4);  \
            pa2 = *(const float4*)(gA + 8);  pa3 = *(const float4*)(gA + 12); \
        }                                                                     \
        if (kc < 31) CP_WAIT(1); else CP_WAIT(0);                             \
        __syncthreads();                                                      \
        const uint32_t bB = sb + OFF_B + (kc & 1) * BSTRIDE;                  \
        PROJ_MMA_PHASE(sb, OFF_AL, bB)                                        \
    }                                                                         \
}

#define PROJ_PROLOGUE()                                                       \
    extern __shared__ char cb[];                                              \
    const uint32_t sb = smem_u32(cb);                                         \
    const int tid = threadIdx.x, lane = tid & 31, wid = tid >> 5;             \
    const int wm = wid & 3, wn = wid >> 2;                                    \
    float acc[2][8][4];                                                       \
    _Pragma("unroll")                                                         \
    for (int i = 0; i < 2; ++i)                                               \
        _Pragma("unroll")                                                     \
        for (int j = 0; j < 8; ++j)                                           \
            _Pragma("unroll")                                                 \
            for (int c = 0; c < 4; ++c) acc[i][j][c] = 0.f;

// ---------------------------------------------------------------------------
// QK projection + per-head LayerNorm. grid (16 heads, 32 mtiles)
// ---------------------------------------------------------------------------
__global__ __launch_bounds__(256, 1) void k_qk_ln(
    const float* __restrict__ X,
    const float* __restrict__ qsc, const float* __restrict__ qbi,
    const float* __restrict__ ksc, const float* __restrict__ kbi)
{
    PROJ_PROLOGUE();
    const int h = blockIdx.x, row0 = blockIdx.y * 128;
    PROJ_BODY_AF32(X + (size_t)row0 * DMODEL, O_WQKH, O_WQKL, 2048, h * 128);

    const int g = lane >> 2, tg = lane & 3;
    const float* sc = wn ? ksc : qsc;
    const float* bi = wn ? kbi : qbi;
    u16* dh = g_pool + (wn ? O_KH : O_QH);
    u16* dl = g_pool + (wn ? O_KL : O_QL);

    #pragma unroll
    for (int i = 0; i < 2; ++i) {
        float s0 = 0.f, s1 = 0.f, q0 = 0.f, q1 = 0.f;
        #pragma unroll
        for (int j = 0; j < 8; ++j) {
            #pragma unroll
            for (int c = 0; c < 4; ++c) acc[i][j][c] *= 0.03125f;
            s0 += acc[i][j][0] + acc[i][j][1];
            s1 += acc[i][j][2] + acc[i][j][3];
            q0 += acc[i][j][0] * acc[i][j][0] + acc[i][j][1] * acc[i][j][1];
            q1 += acc[i][j][2] * acc[i][j][2] + acc[i][j][3] * acc[i][j][3];
        }
        #pragma unroll
        for (int m = 1; m < 4; m <<= 1) {
            s0 += __shfl_xor_sync(0xffffffffu, s0, m);
            s1 += __shfl_xor_sync(0xffffffffu, s1, m);
            q0 += __shfl_xor_sync(0xffffffffu, q0, m);
            q1 += __shfl_xor_sync(0xffffffffu, q1, m);
        }
        float mu0 = s0 * (1.f / 64.f), mu1 = s1 * (1.f / 64.f);
        float iv0 = rsqrtf(q0 * (1.f / 64.f) - mu0 * mu0 + 1e-6f);
        float iv1 = rsqrtf(q1 * (1.f / 64.f) - mu1 * mu1 + 1e-6f);

        int m = row0 + wm * 32 + i * 16 + g;
        int b = m >> 11, l = m & (LSEQ - 1);
        size_t base0 = ((size_t)(b * HEADS + h) * LSEQ + l) * DHEAD;
        size_t base1 = base0 + 8 * DHEAD;

        #pragma unroll
        for (int j = 0; j < 8; ++j) {
            int col = j * 8 + 2 * tg;
            float sc0 = sc[col], sc1 = sc[col + 1], bi0 = bi[col], bi1 = bi[col + 1];
            float y0 = (acc[i][j][0] - mu0) * iv0 * sc0 + bi0;
            float y1 = (acc[i][j][1] - mu0) * iv0 * sc1 + bi1;
            float y2 = (acc[i][j][2] - mu1) * iv1 * sc0 + bi0;
            float y3 = (acc[i][j][3] - mu1) * iv1 * sc1 + bi1;
            float h0, l0, h1, l1, h2, l2, h3, l3;
            bsplit(y0, h0, l0); bsplit(y1, h1, l1); bsplit(y2, h2, l2); bsplit(y3, h3, l3);
            *(uint32_t*)(dh + base0 + col) = pack2(h0, h1);
            *(uint32_t*)(dl + base0 + col) = pack2(l0, l1);
            *(uint32_t*)(dh + base1 + col) = pack2(h2, h3);
            *(uint32_t*)(dl + base1 + col) = pack2(l2, l3);
        }
    }
}

// ---------------------------------------------------------------------------
// V projection -> transposed Vt [bh][d][l] (smem transpose). grid (8, 32)
// ---------------------------------------------------------------------------
__global__ __launch_bounds__(256, 1) void k_v(const float* __restrict__ X)
{
    PROJ_PROLOGUE();
    const int n0b = blockIdx.x * 128, row0 = blockIdx.y * 128;
    PROJ_BODY_AF32(X + (size_t)row0 * DMODEL, O_WVH, O_WVL, 1024, n0b);

    u16* Th = (u16*)cb;                 // [128 n][136 m]
    u16* Tl = (u16*)(cb + 34816);
    const int g = lane >> 2, tg = lane & 3;
    __syncthreads();

    #pragma unroll
    for (int i = 0; i < 2; ++i) {
        int r0 = wm * 32 + i * 16 + g;
        #pragma unroll
        for (int j = 0; j < 8; ++j) {
            int n = wn * 64 + j * 8 + 2 * tg;
            float h0, l0, h1, l1, h2, l2, h3, l3;
            bsplit(acc[i][j][0] * 0.03125f, h0, l0);
            bsplit(acc[i][j][1] * 0.03125f, h1, l1);
            bsplit(acc[i][j][2] * 0.03125f, h2, l2);
            bsplit(acc[i][j][3] * 0.03125f, h3, l3);
            Th[n * 136 + r0]           = bf16_bits(h0);
            Th[(n + 1) * 136 + r0]     = bf16_bits(h1);
            Th[n * 136 + r0 + 8]       = bf16_bits(h2);
            Th[(n + 1) * 136 + r0 + 8] = bf16_bits(h3);
            Tl[n * 136 + r0]           = bf16_bits(bf16_rn(l0));
            Tl[(n + 1) * 136 + r0]     = bf16_bits(bf16_rn(l1));
            Tl[n * 136 + r0 + 8]       = bf16_bits(bf16_rn(l2));
            Tl[(n + 1) * 136 + r0 + 8] = bf16_bits(bf16_rn(l3));
        }
    }
    __syncthreads();

    const int n = tid >> 1, mh = (tid & 1) * 64;
    const int ng = n0b + n, hh = ng >> 6, d = ng & 63;
    const int b = row0 >> 11, l0 = row0 & (LSEQ - 1);
    u16* dsth = g_pool + O_VTH + ((size_t)(b * HEADS + hh) * DHEAD + d) * LSEQ + l0 + mh;
    u16* dstl = g_pool + O_VTL + ((size_t)(b * HEADS + hh) * DHEAD + d) * LSEQ + l0 + mh;
    #pragma unroll
    for (int u = 0; u < 8; ++u) {
        *(uint4*)(dsth + u * 8) = *(uint4*)(Th + n * 136 + mh + u * 8);
        *(uint4*)(dstl + u * 8) = *(uint4*)(Tl + n * 136 + mh + u * 8);
    }
}

// ---------------------------------------------------------------------------
// out projection -> d_out fp32: both operands pre-split, pure cp.async.
// grid (8, 32)
// ---------------------------------------------------------------------------
__global__ __launch_bounds__(256, 1) void k_out(float* __restrict__ out)
{
    PROJ_PROLOGUE();
    const int col0 = blockIdx.x * 128, row0 = blockIdx.y * 128;

    const int m_a = tid >> 1, kq2 = tid & 1;
    const int kb = tid >> 3, nq = tid & 7;
    const int LDBv = 1024;
    const u16* srcAH = g_pool + O_YH + (size_t)(row0 + m_a) * DMODEL + kq2 * 16;
    const u16* srcAL = g_pool + O_YL + (size_t)(row0 + m_a) * DMODEL + kq2 * 16;
    const u16* srcBH = g_pool + O_WOH + (size_t)kb * LDBv + col0 + nq * 16;
    const u16* srcBL = g_pool + O_WOL + (size_t)kb * LDBv + col0 + nq * 16;
    const uint32_t dA = sb + OUT_ABASE + m_a * 80 + kq2 * 32;
    const uint32_t dB = sb + OUT_BBASE + kb * 272 + nq * 32;

    #define CPA_OUT(KCN, DAB)                                                 \
        {                                                                     \
            const u16* _sh = srcAH + (size_t)(KCN) * 32;                      \
            const u16* _sl = srcAL + (size_t)(KCN) * 32;                      \
            cpasync16((DAB), _sh);          cpasync16((DAB) + 16, _sh + 8);   \
            cpasync16((DAB) + OUT_ALO, _sl);                                  \
            cpasync16((DAB) + OUT_ALO + 16, _sl + 8);                         \
        }

    CPA_OUT(0, dA);            CPB(0, dB);            CP_COMMIT();
    CPA_OUT(1, dA + OUT_ASTR); CPB(1, dB + BSTRIDE);  CP_COMMIT();

    #pragma unroll 1
    for (int kc = 0; kc < 32; ++kc) {
        __syncthreads();
        if (kc >= 1 && kc < 31) {
            CPA_OUT(kc + 1, dA + ((kc + 1) & 1) * OUT_ASTR);
            CPB(kc + 1, dB + ((kc + 1) & 1) * BSTRIDE);
            CP_COMMIT();
        }
        if (kc < 31) CP_WAIT(1); else CP_WAIT(0);
        __syncthreads();
        const uint32_t aB = sb + OUT_ABASE + (kc & 1) * OUT_ASTR;
        const uint32_t bB = sb + OUT_BBASE + (kc & 1) * BSTRIDE;
        PROJ_MMA_PHASE(aB, OUT_ALO, bB)
    }

    const int g = lane >> 2, tg = lane & 3;
    #pragma unroll
    for (int i = 0; i < 2; ++i) {
        int r = row0 + wm * 32 + i * 16 + g;
        #pragma unroll
        for (int j = 0; j < 8; ++j) {
            int c = col0 + wn * 64 + j * 8 + 2 * tg;
            float2 v0 = make_float2(acc[i][j][0] * 0.03125f, acc[i][j][1] * 0.03125f);
            float2 v1 = make_float2(acc[i][j][2] * 0.03125f, acc[i][j][3] * 0.03125f);
            *(float2*)(out + (size_t)r * DMODEL + c) = v0;
            *(float2*)(out + (size_t)(r + 8) * DMODEL + c) = v1;
        }
    }
}

// ---------------------------------------------------------------------------
// attention. grid (16 qt, 32 bh), 256 threads, warp w owns q-rows 16w..16w+15.
// Fused S->P->PV per 16-column chunk. Y written as bf16 hi/lo into the pool.
// ---------------------------------------------------------------------------
#define ATTN_SMEM 163840

__device__ __forceinline__ void attn_load_kv(uint32_t sbuf, int bh, int jt, int tid)
{
    {
        const int r = tid >> 1, cbx = (tid & 1) * 4;
        const size_t go = ((size_t)bh * LSEQ + jt * 128 + r) * DHEAD + cbx * 8;
        const uint32_t base = sbuf + r * 128;
        #pragma unroll
        for (int c = 0; c < 4; ++c) {
            uint32_t cc = ((uint32_t)(cbx + c) ^ (r & 7)) * 16;
            cpasync16(base + cc,         g_pool + O_KH + go + c * 8);
            cpasync16(base + 16384 + cc, g_pool + O_KL + go + c * 8);
        }
    }
    {
        const int r = tid >> 2, cbx = (tid & 3) * 4;
        const size_t go = ((size_t)bh * DHEAD + r) * LSEQ + jt * 128 + cbx * 8;
        const uint32_t base = sbuf + 32768 + r * 256;
        #pragma unroll
        for (int c = 0; c < 4; ++c) {
            uint32_t cc = ((uint32_t)(cbx + c) ^ ((r & 7) << 1)) * 16;
            cpasync16(base + cc,         g_pool + O_VTH + go + c * 8);
            cpasync16(base + 16384 + cc, g_pool + O_VTL + go + c * 8);
        }
    }
    CP_COMMIT();
}

__global__ __launch_bounds__(256, 1) void k_attn()
{
    extern __shared__ char smraw[];
    const uint32_t sb = smem_u32(smraw);
    const int qt = (int)gridDim.x - 1 - (int)blockIdx.x;   // big tiles first
    const int bh = blockIdx.y;
    const int tid = threadIdx.x, lane = tid & 31, wid = tid >> 5;
    const int g = lane >> 2, tg = lane & 3;

    // stage Q (group 1)
    {
        const int r = tid >> 1, cbx = (tid & 1) * 4;
        const size_t go = ((size_t)bh * LSEQ + qt * 128 + r) * DHEAD + cbx * 8;
        const uint32_t base = sb + r * 128;
        #pragma unroll
        for (int c = 0; c < 4; ++c) {
            uint32_t cc = ((uint32_t)(cbx + c) ^ (r & 7)) * 16;
            cpasync16(base + cc,         g_pool + O_QH + go + c * 8);
            cpasync16(base + 16384 + cc, g_pool + O_QL + go + c * 8);
        }
        CP_COMMIT();
    }
    attn_load_kv(sb + 32768, bh, 0, tid);

    CP_WAIT(1);
    __syncthreads();

    uint32_t qh[4][4], ql[4][4];
    {
        int row = wid * 16 + (lane & 15);
        #pragma unroll
        for (int l = 0; l < 4; ++l) {
            int chunk = 2 * l + (lane >> 4);
            uint32_t a = sb + row * 128 + ((chunk ^ (row & 7)) * 16);
            LDSM4(qh[l][0], qh[l][1], qh[l][2], qh[l][3], a);
            LDSM4(ql[l][0], ql[l][1], ql[l][2], ql[l][3], a + 16384);
        }
    }

    float o[8][4];
    #pragma unroll
    for (int j = 0; j < 8; ++j)
        #pragma unroll
        for (int c = 0; c < 4; ++c) o[j][c] = 0.f;
    float den0 = 0.f, den1 = 0.f;

    const int rq = wid * 16 + g;

    int buf = 0;
    #pragma unroll 1
    for (int jt = 0; jt <= qt; ++jt) {
        if (jt < qt) { attn_load_kv(sb + 32768 + (buf ^ 1) * 65536, bh, jt + 1, tid); CP_WAIT(1); }
        else CP_WAIT(0);
        __syncthreads();
        const uint32_t sK = sb + 32768 + buf * 65536;
        const uint32_t sV = sK + 32768;

        const bool dg = (jt == qt);
        const int kkmax = dg ? wid : 7;

        #pragma unroll 1
        for (int kk = 0; kk <= kkmax; ++kk) {
            float s0[4] = {0.f, 0.f, 0.f, 0.f};
            float s1[4] = {0.f, 0.f, 0.f, 0.f};
            {
                int row = kk * 16 + (lane & 7) + ((lane >> 4) << 3);
                #pragma unroll
                for (int l = 0; l < 4; ++l) {
                    int chunk = 2 * l + ((lane >> 3) & 1);
                    uint32_t a = sK + row * 128 + ((chunk ^ (row & 7)) * 16);
                    uint32_t b0, b1, b2, b3, c0, c1, c2, c3;
                    LDSM4(b0, b1, b2, b3, a);
                    LDSM4(c0, c1, c2, c3, a + 16384);
                    MMA4(s0[0], s0[1], s0[2], s0[3], qh[l][0], qh[l][1], qh[l][2], qh[l][3], b0, b1);
                    MMA4(s0[0], s0[1], s0[2], s0[3], ql[l][0], ql[l][1], ql[l][2], ql[l][3], b0, b1);
                    MMA4(s0[0], s0[1], s0[2], s0[3], qh[l][0], qh[l][1], qh[l][2], qh[l][3], c0, c1);
                    MMA4(s1[0], s1[1], s1[2], s1[3], qh[l][0], qh[l][1], qh[l][2], qh[l][3], b2, b3);
                    MMA4(s1[0], s1[1], s1[2], s1[3], ql[l][0], ql[l][1], ql[l][2], ql[l][3], b2, b3);
                    MMA4(s1[0], s1[1], s1[2], s1[3], qh[l][0], qh[l][1], qh[l][2], qh[l][3], c2, c3);
                }
            }

            uint32_t p0, p1, p2, p3, r0, r1, r2, r3;
            {
                float e0 = fast_exp(s0[0] * 0.015625f);
                float e1 = fast_exp(s0[1] * 0.015625f);
                float e2 = fast_exp(s0[2] * 0.015625f);
                float e3 = fast_exp(s0[3] * 0.015625f);
                float f0 = fast_exp(s1[0] * 0.015625f);
                float f1 = fast_exp(s1[1] * 0.015625f);
                float f2 = fast_exp(s1[2] * 0.015625f);
                float f3 = fast_exp(s1[3] * 0.015625f);
                if (dg) {
                    int c0i = kk * 16 + 2 * tg;
                    if (c0i > rq)          e0 = 0.f;
                    if (c0i + 1 > rq)      e1 = 0.f;
                    if (c0i > rq + 8)      e2 = 0.f;
                    if (c0i + 1 > rq + 8)  e3 = 0.f;
                    if (c0i + 8 > rq)      f0 = 0.f;
                    if (c0i + 9 > rq)      f1 = 0.f;
                    if (c0i + 8 > rq + 8)  f2 = 0.f;
                    if (c0i + 9 > rq + 8)  f3 = 0.f;
                }
                den0 += e0 + e1 + f0 + f1;
                den1 += e2 + e3 + f2 + f3;
                float h0, l0, h1, l1;
                bsplit(e0, h0, l0); bsplit(e1, h1, l1);
                p0 = pack2(h0, h1); r0 = pack2(l0, l1);
                bsplit(e2, h0, l0); bsplit(e3, h1, l1);
                p1 = pack2(h0, h1); r1 = pack2(l0, l1);
                bsplit(f0, h0, l0); bsplit(f1, h1, l1);
                p2 = pack2(h0, h1); r2 = pack2(l0, l1);
                bsplit(f2, h0, l0); bsplit(f3, h1, l1);
                p3 = pack2(h0, h1); r3 = pack2(l0, l1);
            }

            {
                int row = (lane & 7) + ((lane >> 4) << 3);
                int chunk = 2 * kk + ((lane >> 3) & 1);
                #pragma unroll
                for (int np = 0; np < 4; ++np) {
                    int r2i = np * 16 + row;
                    uint32_t a = sV + r2i * 256 + ((chunk ^ ((r2i & 7) << 1)) * 16);
                    uint32_t vb0, vb1, vb2, vb3, vc0, vc1, vc2, vc3;
                    LDSM4(vb0, vb1, vb2, vb3, a);
                    LDSM4(vc0, vc1, vc2, vc3, a + 16384);
                    MMA4(o[2*np][0], o[2*np][1], o[2*np][2], o[2*np][3], p0, p1, p2, p3, vb0, vb1);
                    MMA4(o[2*np][0], o[2*np][1], o[2*np][2], o[2*np][3], r0, r1, r2, r3, vb0, vb1);
                    MMA4(o[2*np][0], o[2*np][1], o[2*np][2], o[2*np][3], p0, p1, p2, p3, vc0, vc1);
                    MMA4(o[2*np+1][0], o[2*np+1][1], o[2*np+1][2], o[2*np+1][3], p0, p1, p2, p3, vb2, vb3);
                    MMA4(o[2*np+1][0], o[2*np+1][1], o[2*np+1][2], o[2*np+1][3], r0, r1, r2, r3, vb2, vb3);
                    MMA4(o[2*np+1][0], o[2*np+1][1], o[2*np+1][2], o[2*np+1][3], p0, p1, p2, p3, vc2, vc3);
                }
            }
        }
        __syncthreads();
        buf ^= 1;
    }

    #pragma unroll
    for (int m = 1; m < 4; m <<= 1) {
        den0 += __shfl_xor_sync(0xffffffffu, den0, m);
        den1 += __shfl_xor_sync(0xffffffffu, den1, m);
    }
    const float inv0 = 1.f / den0, inv1 = 1.f / den1;

    const int b = bh >> 4, h = bh & 15;
    const size_t m0 = (size_t)b * LSEQ + qt * 128 + wid * 16 + g;
    u16* Yh = g_pool + O_YH;
    u16* Yl = g_pool + O_YL;
    #pragma unroll
    for (int j = 0; j < 8; ++j) {
        int d = j * 8 + 2 * tg;
        float h0, l0, h1, l1, h2, l2, h3, l3;
        bsplit(o[j][0] * inv0, h0, l0);
        bsplit(o[j][1] * inv0, h1, l1);
        bsplit(o[j][2] * inv1, h2, l2);
        bsplit(o[j][3] * inv1, h3, l3);
        *(uint32_t*)(Yh + m0 * DMODEL + h * 64 + d) = pack2(h0, h1);
        *(uint32_t*)(Yl + m0 * DMODEL + h * 64 + d) = pack2(l0, l1);
        *(uint32_t*)(Yh + (m0 + 8) * DMODEL + h * 64 + d) = pack2(h2, h3);
        *(uint32_t*)(Yl + (m0 + 8) * DMODEL + h * 64 + d) = pack2(l2, l3);
    }
}

// ---------------------------------------------------------------------------
extern "C" void kernel_launch(void* const* d_in, const int* in_sizes, int n_in,
                              void* d_out, int out_size)
{
    const float* X    = (const float*)d_in[0];
    const float* Wqk  = (const float*)d_in[1];
    const float* Wv   = (const float*)d_in[2];
    const float* Wout = (const float*)d_in[3];
    const float* qsc  = (const float*)d_in[4];
    const float* qbi  = (const float*)d_in[5];
    const float* ksc  = (const float*)d_in[6];
    const float* kbi  = (const float*)d_in[7];
    float* out = (float*)d_out;

    cudaFuncSetAttribute(k_qk_ln, cudaFuncAttributeMaxDynamicSharedMemorySize, PROJ_SMEM);
    cudaFuncSetAttribute(k_v,     cudaFuncAttributeMaxDynamicSharedMemorySize, KV_SMEM);
    cudaFuncSetAttribute(k_out,   cudaFuncAttributeMaxDynamicSharedMemorySize, KOUT_SMEM);
    cudaFuncSetAttribute(k_attn,  cudaFuncAttributeMaxDynamicSharedMemorySize, ATTN_SMEM);

    k_wsplit<<<2048, 256>>>(Wqk,  O_WQKH, O_WQKL, 2048 * 1024 / 4);
    k_wsplit<<<1024, 256>>>(Wv,   O_WVH,  O_WVL,  1024 * 1024 / 4);

    k_qk_ln<<<dim3(HEADS, MROWS / 128), 256, PROJ_SMEM>>>(X, qsc, qbi, ksc, kbi);
    k_v<<<dim3(8, MROWS / 128), 256, KV_SMEM>>>(X);
    k_attn<<<dim3(LSEQ / 128, BH), 256, ATTN_SMEM>>>();
    k_wsplit<<<1024, 256>>>(Wout, O_WOH, O_WOL, 1024 * 1024 / 4);   // into dead Q region
    k_out<<<dim3(8, MROWS / 128), 256, KOUT_SMEM>>>(out);
}

// round 12
// speedup vs baseline: 2.4283x; 1.0162x over previous
#include <cuda_runtime.h>
#include <cstdint>
#include <cstddef>

#define LSEQ   2048
#define HEADS  16
#define DHEAD  64
#define DMODEL 1024
#define MROWS  4096
#define BH     32

typedef unsigned short u16;   // bf16 bit pattern

// ---------------- 64 MiB aliased pool (empirical cap: 64 MiB passes, 96 trips)
#define POOL_ELEMS (32u * 1024u * 1024u)
__device__ __align__(256) u16 g_pool[POOL_ELEMS];

#define O_QH   (0ul)
#define O_QL   (4ul  << 20)
#define O_KH   (8ul  << 20)
#define O_KL   (12ul << 20)
#define O_VTH  (16ul << 20)
#define O_VTL  (20ul << 20)
#define O_WQKH (24ul << 20)
#define O_WQKL (26ul << 20)
#define O_WVH  (28ul << 20)
#define O_WVL  (29ul << 20)
#define O_YH   (24ul << 20)
#define O_YL   (28ul << 20)
#define O_WOH  (0ul)
#define O_WOL  (1ul << 20)

// ---------------- helpers --------------------------------------------------
__device__ __forceinline__ uint32_t smem_u32(const void* p) {
    uint32_t a;
    asm("{ .reg .u64 t; cvta.to.shared.u64 t, %1; cvt.u32.u64 %0, t; }" : "=r"(a) : "l"(p));
    return a;
}

#define LDSM4(r0, r1, r2, r3, addr) \
    asm volatile("ldmatrix.sync.aligned.m8n8.x4.shared.b16 {%0,%1,%2,%3}, [%4];" \
        : "=r"(r0), "=r"(r1), "=r"(r2), "=r"(r3) : "r"(addr))

#define LDSM4T(r0, r1, r2, r3, addr) \
    asm volatile("ldmatrix.sync.aligned.m8n8.x4.trans.shared.b16 {%0,%1,%2,%3}, [%4];" \
        : "=r"(r0), "=r"(r1), "=r"(r2), "=r"(r3) : "r"(addr))

#define MMA4(c0, c1, c2, c3, a0, a1, a2, a3, b0, b1) \
    asm volatile("mma.sync.aligned.m16n8k16.row.col.f32.bf16.bf16.f32 " \
        "{%0,%1,%2,%3}, {%4,%5,%6,%7}, {%8,%9}, {%0,%1,%2,%3};" \
        : "+f"(c0), "+f"(c1), "+f"(c2), "+f"(c3) \
        : "r"(a0), "r"(a1), "r"(a2), "r"(a3), "r"(b0), "r"(b1))

__device__ __forceinline__ void cpasync16(uint32_t dst, const void* src) {
    asm volatile("cp.async.cg.shared.global [%0], [%1], 16;" :: "r"(dst), "l"(src));
}
#define CP_COMMIT() asm volatile("cp.async.commit_group;" ::: "memory")
#define CP_WAIT(n)  asm volatile("cp.async.wait_group %0;" :: "n"(n) : "memory")

__device__ __forceinline__ float fast_exp(float x) {
    float y = x * 1.4426950408889634f;
    float z = y + 12582912.0f;
    int   n = __float_as_int(z) - 0x4B400000;
    float f = y - (z - 12582912.0f);
    float p = 1.3333558146e-3f;
    p = fmaf(p, f, 9.6181291076e-3f);
    p = fmaf(p, f, 5.5504108665e-2f);
    p = fmaf(p, f, 2.4022650696e-1f);
    p = fmaf(p, f, 6.9314718056e-1f);
    p = fmaf(p, f, 1.0f);
    return __int_as_float(__float_as_int(p) + (n << 23));
}
__device__ __forceinline__ uint32_t pack2(float a, float b) {
    uint32_t r;
    asm("cvt.rn.bf16x2.f32 %0, %1, %2;" : "=r"(r) : "f"(b), "f"(a));
    return r;
}
__device__ __forceinline__ float bf16_rn(float v) {
    uint32_t u = __float_as_uint(v);
    return __uint_as_float((u + 0x7FFFu + ((u >> 16) & 1u)) & 0xFFFF0000u);
}
__device__ __forceinline__ void bsplit(float v, float& hi, float& lo) {
    hi = bf16_rn(v);
    lo = v - hi;
}
__device__ __forceinline__ u16 bf16_bits(float v_already_rounded) {
    return (u16)(__float_as_uint(v_already_rounded) >> 16);
}

// ---------------------------------------------------------------------------
// weight splitter: fp32 [n] -> hi/lo bf16 at pool offsets
// ---------------------------------------------------------------------------
__global__ void k_wsplit(const float* __restrict__ s, size_t offh, size_t offl, int n4)
{
    int i = blockIdx.x * blockDim.x + threadIdx.x;
    if (i >= n4) return;
    float4 v = ((const float4*)s)[i];
    float h0, l0, h1, l1, h2, l2, h3, l3;
    bsplit(v.x, h0, l0); bsplit(v.y, h1, l1); bsplit(v.z, h2, l2); bsplit(v.w, h3, l3);
    uint2 uh, ul;
    uh.x = pack2(h0, h1); uh.y = pack2(h2, h3);
    ul.x = pack2(l0, l1); ul.y = pack2(l2, l3);
    ((uint2*)(g_pool + offh))[i] = uh;
    ((uint2*)(g_pool + offl))[i] = ul;
}

// ===========================================================================
// Projections: 512 threads / 16 warps, C tile 128x128, warp tile 32x32.
// wm = wid & 3 (m block of 32 rows), wn = wid >> 2 (n block of 32 cols).
// smem: A hi[128x80B]@0, A lo @10240; B double bufs @20480, stride 17408
// (hi 8704 = 32x272B rows, lo at +8704).
// ===========================================================================
#define OFF_AL   10240
#define OFF_B    20480
#define BSTRIDE  17408
#define BLO      8704
#define PROJ_SMEM 55296
#define KV_SMEM   69632
#define OUT_ABASE 0
#define OUT_ASTR  20480
#define OUT_ALO   10240
#define OUT_BBASE 40960
#define KOUT_SMEM 75776

#define CVT8_STS(dsthi, dstlo, va, vb)                                        \
    {                                                                         \
        float h0,l0,h1,l1,h2,l2,h3,l3,h4,l4,h5,l5,h6,l6,h7,l7;                \
        bsplit(va.x,h0,l0); bsplit(va.y,h1,l1); bsplit(va.z,h2,l2);           \
        bsplit(va.w,h3,l3); bsplit(vb.x,h4,l4); bsplit(vb.y,h5,l5);           \
        bsplit(vb.z,h6,l6); bsplit(vb.w,h7,l7);                               \
        uint4 uh, ul;                                                         \
        uh.x = pack2(h0,h1); uh.y = pack2(h2,h3);                             \
        uh.z = pack2(h4,h5); uh.w = pack2(h6,h7);                             \
        ul.x = pack2(l0,l1); ul.y = pack2(l2,l3);                             \
        ul.z = pack2(l4,l5); ul.w = pack2(l6,l7);                             \
        *(uint4*)(dsthi) = uh;                                                \
        *(uint4*)(dstlo) = ul;                                                \
    }

// one B chunk (hi+lo): 512 threads x 16B covers 32x128 u16 per half
#define CPB(KCN, DB)                                                          \
    {                                                                         \
        const u16* _sh = srcBH + (size_t)(KCN) * 32 * LDBv;                   \
        const u16* _sl = srcBL + (size_t)(KCN) * 32 * LDBv;                   \
        cpasync16((DB), _sh);                                                 \
        cpasync16((DB) + BLO, _sl);                                           \
    }

// MMA phase: warp tile 32x32, ks in {0,1}, np in {0,1}
#define PROJ_MMA_PHASE(AB0, ALO2, BB)                                         \
    _Pragma("unroll")                                                         \
    for (int ks = 0; ks < 2; ++ks) {                                          \
        uint32_t ah[2][4], al[2][4];                                          \
        _Pragma("unroll")                                                     \
        for (int i = 0; i < 2; ++i) {                                         \
            int row = wm * 32 + i * 16 + (lane & 15);                         \
            uint32_t a = (AB0) + row * 80 + (ks * 2 + (lane >> 4)) * 16;      \
            LDSM4(ah[i][0], ah[i][1], ah[i][2], ah[i][3], a);                 \
            LDSM4(al[i][0], al[i][1], al[i][2], al[i][3], a + (ALO2));        \
        }                                                                     \
        _Pragma("unroll")                                                     \
        for (int np = 0; np < 2; ++np) {                                      \
            int tilei = lane >> 3;                                            \
            int krow = ks * 16 + (tilei & 1) * 8 + (lane & 7);                \
            int ncol = wn * 32 + np * 16 + (tilei >> 1) * 8;                  \
            uint32_t a = (BB) + krow * 272 + ncol * 2;                        \
            uint32_t b0, b1, b2, b3, c0, c1, c2, c3;                          \
            LDSM4T(b0, b1, b2, b3, a);                                        \
            LDSM4T(c0, c1, c2, c3, a + BLO);                                  \
            _Pragma("unroll")                                                 \
            for (int i = 0; i < 2; ++i) {                                     \
                MMA4(acc[i][2*np][0], acc[i][2*np][1],                        \
                     acc[i][2*np][2], acc[i][2*np][3],                        \
                     ah[i][0], ah[i][1], ah[i][2], ah[i][3], b0, b1);         \
                MMA4(acc[i][2*np][0], acc[i][2*np][1],                        \
                     acc[i][2*np][2], acc[i][2*np][3],                        \
                     al[i][0], al[i][1], al[i][2], al[i][3], b0, b1);         \
                MMA4(acc[i][2*np][0], acc[i][2*np][1],                        \
                     acc[i][2*np][2], acc[i][2*np][3],                        \
                     ah[i][0], ah[i][1], ah[i][2], ah[i][3], c0, c1);         \
                MMA4(acc[i][2*np+1][0], acc[i][2*np+1][1],                    \
                     acc[i][2*np+1][2], acc[i][2*np+1][3],                    \
                     ah[i][0], ah[i][1], ah[i][2], ah[i][3], b2, b3);         \
                MMA4(acc[i][2*np+1][0], acc[i][2*np+1][1],                    \
                     acc[i][2*np+1][2], acc[i][2*np+1][3],                    \
                     al[i][0], al[i][1], al[i][2], al[i][3], b2, b3);         \
                MMA4(acc[i][2*np+1][0], acc[i][2*np+1][1],                    \
                     acc[i][2*np+1][2], acc[i][2*np+1][3],                    \
                     ah[i][0], ah[i][1], ah[i][2], ah[i][3], c2, c3);         \
            }                                                                 \
        }                                                                     \
    }

// Projection with fp32 A (in-kernel split) + pre-split B via cp.async.
#define PROJ_BODY_AF32(APTR, WHOFF, WLOFF, LDB, N0)                           \
{                                                                             \
    const int r_a = tid >> 2, kq_a = (tid & 3) * 8;                           \
    const int kb = tid >> 4, nq = tid & 15;                                   \
    const int LDBv = (LDB);                                                   \
    const float* gA = (APTR) + (size_t)r_a * DMODEL + kq_a;                   \
    const u16* srcBH = g_pool + (WHOFF) + (size_t)kb * LDBv + (N0) + nq * 8;  \
    const u16* srcBL = g_pool + (WLOFF) + (size_t)kb * LDBv + (N0) + nq * 8;  \
    float4 pa0 = *(const float4*)(gA + 0),  pa1 = *(const float4*)(gA + 4);   \
    char* aH = cb + r_a * 80 + (tid & 3) * 16;                                \
    const uint32_t dB = sb + OFF_B + kb * 272 + nq * 16;                      \
    CPB(0, dB);            CP_COMMIT();                                       \
    CPB(1, dB + BSTRIDE);  CP_COMMIT();                                       \
    _Pragma("unroll 1")                                                       \
    for (int kc = 0; kc < 32; ++kc) {                                         \
        __syncthreads();                                                      \
        if (kc >= 1 && kc < 31) {                                             \
            CPB(kc + 1, dB + ((kc + 1) & 1) * BSTRIDE);  CP_COMMIT();         \
        }                                                                     \
        CVT8_STS(aH, aH + OFF_AL, pa0, pa1);                                  \
        if (kc < 31) {                                                        \
            gA += 32;                                                         \
            pa0 = *(const float4*)(gA + 0);  pa1 = *(const float4*)(gA + 4);  \
        }                                                                     \
        if (kc < 31) CP_WAIT(1); else CP_WAIT(0);                             \
        __syncthreads();                                                      \
        const uint32_t bB = sb + OFF_B + (kc & 1) * BSTRIDE;                  \
        PROJ_MMA_PHASE(sb, OFF_AL, bB)                                        \
    }                                                                         \
}

#define PROJ_PROLOGUE()                                                       \
    extern __shared__ char cb[];                                              \
    const uint32_t sb = smem_u32(cb);                                         \
    const int tid = threadIdx.x, lane = tid & 31, wid = tid >> 5;             \
    const int wm = wid & 3, wn = wid >> 2;                                    \
    float acc[2][4][4];                                                       \
    _Pragma("unroll")                                                         \
    for (int i = 0; i < 2; ++i)                                               \
        _Pragma("unroll")                                                     \
        for (int j = 0; j < 4; ++j)                                           \
            _Pragma("unroll")                                                 \
            for (int c = 0; c < 4; ++c) acc[i][j][c] = 0.f;

// ---------------------------------------------------------------------------
// QK projection + per-head LayerNorm. grid (16 heads, 32 mtiles), 512 thr.
// Warp pair (wn, wn^1) shares each 64-dim LN row: cross-warp smem reduction.
// ---------------------------------------------------------------------------
__global__ __launch_bounds__(512, 1) void k_qk_ln(
    const float* __restrict__ X,
    const float* __restrict__ qsc, const float* __restrict__ qbi,
    const float* __restrict__ ksc, const float* __restrict__ kbi)
{
    PROJ_PROLOGUE();
    const int h = blockIdx.x, row0 = blockIdx.y * 128;
    PROJ_BODY_AF32(X + (size_t)row0 * DMODEL, O_WQKH, O_WQKL, 2048, h * 128);

    const int g = lane >> 2, tg = lane & 3;
    const int isK = wn >> 1;           // wn 0,1 -> q half; 2,3 -> k half
    const int colbase = (wn & 1) * 32; // within the 64-dim half
    const float* sc = isK ? ksc : qsc;
    const float* bi = isK ? kbi : qbi;
    u16* dh = g_pool + (isK ? O_KH : O_QH);
    u16* dl = g_pool + (isK ? O_KL : O_QL);

    float* Ss = (float*)cb;        // [4 wn][128 rows]
    float* Sq = Ss + 512;
    __syncthreads();               // A/B smem regions now reusable

    float ps[2][4];
    #pragma unroll
    for (int i = 0; i < 2; ++i) {
        float s0 = 0.f, s1 = 0.f, q0 = 0.f, q1 = 0.f;
        #pragma unroll
        for (int j = 0; j < 4; ++j) {
            #pragma unroll
            for (int c = 0; c < 4; ++c) acc[i][j][c] *= 0.03125f;
            s0 += acc[i][j][0] + acc[i][j][1];
            s1 += acc[i][j][2] + acc[i][j][3];
            q0 += acc[i][j][0] * acc[i][j][0] + acc[i][j][1] * acc[i][j][1];
            q1 += acc[i][j][2] * acc[i][j][2] + acc[i][j][3] * acc[i][j][3];
        }
        #pragma unroll
        for (int m = 1; m < 4; m <<= 1) {
            s0 += __shfl_xor_sync(0xffffffffu, s0, m);
            s1 += __shfl_xor_sync(0xffffffffu, s1, m);
            q0 += __shfl_xor_sync(0xffffffffu, q0, m);
            q1 += __shfl_xor_sync(0xffffffffu, q1, m);
        }
        ps[i][0] = s0; ps[i][1] = s1; ps[i][2] = q0; ps[i][3] = q1;
        if (tg == 0) {
            int r0 = wm * 32 + i * 16 + g;
            Ss[wn * 128 + r0]     = s0;
            Ss[wn * 128 + r0 + 8] = s1;
            Sq[wn * 128 + r0]     = q0;
            Sq[wn * 128 + r0 + 8] = q1;
        }
    }
    __syncthreads();

    #pragma unroll
    for (int i = 0; i < 2; ++i) {
        int r0 = wm * 32 + i * 16 + g;
        float s0 = ps[i][0] + Ss[(wn ^ 1) * 128 + r0];
        float s1 = ps[i][1] + Ss[(wn ^ 1) * 128 + r0 + 8];
        float q0 = ps[i][2] + Sq[(wn ^ 1) * 128 + r0];
        float q1 = ps[i][3] + Sq[(wn ^ 1) * 128 + r0 + 8];
        float mu0 = s0 * (1.f / 64.f), mu1 = s1 * (1.f / 64.f);
        float iv0 = rsqrtf(q0 * (1.f / 64.f) - mu0 * mu0 + 1e-6f);
        float iv1 = rsqrtf(q1 * (1.f / 64.f) - mu1 * mu1 + 1e-6f);

        int m = row0 + r0;
        int b = m >> 11, l = m & (LSEQ - 1);
        size_t base0 = ((size_t)(b * HEADS + h) * LSEQ + l) * DHEAD;
        size_t base1 = base0 + 8 * DHEAD;

        #pragma unroll
        for (int j = 0; j < 4; ++j) {
            int col = colbase + j * 8 + 2 * tg;
            float sc0 = sc[col], sc1 = sc[col + 1], bi0 = bi[col], bi1 = bi[col + 1];
            float y0 = (acc[i][j][0] - mu0) * iv0 * sc0 + bi0;
            float y1 = (acc[i][j][1] - mu0) * iv0 * sc1 + bi1;
            float y2 = (acc[i][j][2] - mu1) * iv1 * sc0 + bi0;
            float y3 = (acc[i][j][3] - mu1) * iv1 * sc1 + bi1;
            float h0, l0, h1, l1, h2, l2, h3, l3;
            bsplit(y0, h0, l0); bsplit(y1, h1, l1); bsplit(y2, h2, l2); bsplit(y3, h3, l3);
            *(uint32_t*)(dh + base0 + col) = pack2(h0, h1);
            *(uint32_t*)(dl + base0 + col) = pack2(l0, l1);
            *(uint32_t*)(dh + base1 + col) = pack2(h2, h3);
            *(uint32_t*)(dl + base1 + col) = pack2(l2, l3);
        }
    }
}

// ---------------------------------------------------------------------------
// V projection -> transposed Vt [bh][d][l] (smem transpose). grid (8, 32), 512 thr
// ---------------------------------------------------------------------------
__global__ __launch_bounds__(512, 1) void k_v(const float* __restrict__ X)
{
    PROJ_PROLOGUE();
    const int n0b = blockIdx.x * 128, row0 = blockIdx.y * 128;
    PROJ_BODY_AF32(X + (size_t)row0 * DMODEL, O_WVH, O_WVL, 1024, n0b);

    u16* Th = (u16*)cb;                 // [128 n][136 m]
    u16* Tl = Th + 128 * 136;
    const int g = lane >> 2, tg = lane & 3;
    __syncthreads();

    #pragma unroll
    for (int i = 0; i < 2; ++i) {
        int r0 = wm * 32 + i * 16 + g;
        #pragma unroll
        for (int j = 0; j < 4; ++j) {
            int n = wn * 32 + j * 8 + 2 * tg;
            float h0, l0, h1, l1, h2, l2, h3, l3;
            bsplit(acc[i][j][0] * 0.03125f, h0, l0);
            bsplit(acc[i][j][1] * 0.03125f, h1, l1);
            bsplit(acc[i][j][2] * 0.03125f, h2, l2);
            bsplit(acc[i][j][3] * 0.03125f, h3, l3);
            Th[n * 136 + r0]           = bf16_bits(h0);
            Th[(n + 1) * 136 + r0]     = bf16_bits(h1);
            Th[n * 136 + r0 + 8]       = bf16_bits(h2);
            Th[(n + 1) * 136 + r0 + 8] = bf16_bits(h3);
            Tl[n * 136 + r0]           = bf16_bits(bf16_rn(l0));
            Tl[(n + 1) * 136 + r0]     = bf16_bits(bf16_rn(l1));
            Tl[n * 136 + r0 + 8]       = bf16_bits(bf16_rn(l2));
            Tl[(n + 1) * 136 + r0 + 8] = bf16_bits(bf16_rn(l3));
        }
    }
    __syncthreads();

    const int n = tid >> 2, mh = (tid & 3) * 32;
    const int ng = n0b + n, hh = ng >> 6, d = ng & 63;
    const int b = row0 >> 11, l0 = row0 & (LSEQ - 1);
    u16* dsth = g_pool + O_VTH + ((size_t)(b * HEADS + hh) * DHEAD + d) * LSEQ + l0 + mh;
    u16* dstl = g_pool + O_VTL + ((size_t)(b * HEADS + hh) * DHEAD + d) * LSEQ + l0 + mh;
    #pragma unroll
    for (int u = 0; u < 4; ++u) {
        *(uint4*)(dsth + u * 8) = *(uint4*)(Th + n * 136 + mh + u * 8);
        *(uint4*)(dstl + u * 8) = *(uint4*)(Tl + n * 136 + mh + u * 8);
    }
}

// ---------------------------------------------------------------------------
// out projection -> d_out fp32: both operands pre-split. grid (8, 32), 512 thr
// ---------------------------------------------------------------------------
__global__ __launch_bounds__(512, 1) void k_out(float* __restrict__ out)
{
    PROJ_PROLOGUE();
    const int col0 = blockIdx.x * 128, row0 = blockIdx.y * 128;

    const int m_a = tid >> 2, kq = tid & 3;
    const int kb = tid >> 4, nq = tid & 15;
    const int LDBv = 1024;
    const u16* srcAH = g_pool + O_YH + (size_t)(row0 + m_a) * DMODEL + kq * 8;
    const u16* srcAL = g_pool + O_YL + (size_t)(row0 + m_a) * DMODEL + kq * 8;
    const u16* srcBH = g_pool + O_WOH + (size_t)kb * LDBv + col0 + nq * 8;
    const u16* srcBL = g_pool + O_WOL + (size_t)kb * LDBv + col0 + nq * 8;
    const uint32_t dA = sb + OUT_ABASE + m_a * 80 + kq * 16;
    const uint32_t dB = sb + OUT_BBASE + kb * 272 + nq * 16;

    #define CPA_OUT(KCN, DAB)                                                 \
        {                                                                     \
            cpasync16((DAB),           srcAH + (size_t)(KCN) * 32);           \
            cpasync16((DAB) + OUT_ALO, srcAL + (size_t)(KCN) * 32);           \
        }

    CPA_OUT(0, dA);            CPB(0, dB);            CP_COMMIT();
    CPA_OUT(1, dA + OUT_ASTR); CPB(1, dB + BSTRIDE);  CP_COMMIT();

    #pragma unroll 1
    for (int kc = 0; kc < 32; ++kc) {
        __syncthreads();
        if (kc >= 1 && kc < 31) {
            CPA_OUT(kc + 1, dA + ((kc + 1) & 1) * OUT_ASTR);
            CPB(kc + 1, dB + ((kc + 1) & 1) * BSTRIDE);
            CP_COMMIT();
        }
        if (kc < 31) CP_WAIT(1); else CP_WAIT(0);
        __syncthreads();
        const uint32_t aB = sb + OUT_ABASE + (kc & 1) * OUT_ASTR;
        const uint32_t bB = sb + OUT_BBASE + (kc & 1) * BSTRIDE;
        PROJ_MMA_PHASE(aB, OUT_ALO, bB)
    }

    const int g = lane >> 2, tg = lane & 3;
    #pragma unroll
    for (int i = 0; i < 2; ++i) {
        int r = row0 + wm * 32 + i * 16 + g;
        #pragma unroll
        for (int j = 0; j < 4; ++j) {
            int c = col0 + wn * 32 + j * 8 + 2 * tg;
            float2 v0 = make_float2(acc[i][j][0] * 0.03125f, acc[i][j][1] * 0.03125f);
            float2 v1 = make_float2(acc[i][j][2] * 0.03125f, acc[i][j][3] * 0.03125f);
            *(float2*)(out + (size_t)r * DMODEL + c) = v0;
            *(float2*)(out + (size_t)(r + 8) * DMODEL + c) = v1;
        }
    }
}

// ---------------------------------------------------------------------------
// attention — UNCHANGED from the passing R10 kernel.
// grid (16 qt, 32 bh), 256 threads, warp w owns q-rows 16w..16w+15.
// ---------------------------------------------------------------------------
#define ATTN_SMEM 163840

__device__ __forceinline__ void attn_load_kv(uint32_t sbuf, int bh, int jt, int tid)
{
    {
        const int r = tid >> 1, cbx = (tid & 1) * 4;
        const size_t go = ((size_t)bh * LSEQ + jt * 128 + r) * DHEAD + cbx * 8;
        const uint32_t base = sbuf + r * 128;
        #pragma unroll
        for (int c = 0; c < 4; ++c) {
            uint32_t cc = ((uint32_t)(cbx + c) ^ (r & 7)) * 16;
            cpasync16(base + cc,         g_pool + O_KH + go + c * 8);
            cpasync16(base + 16384 + cc, g_pool + O_KL + go + c * 8);
        }
    }
    {
        const int r = tid >> 2, cbx = (tid & 3) * 4;
        const size_t go = ((size_t)bh * DHEAD + r) * LSEQ + jt * 128 + cbx * 8;
        const uint32_t base = sbuf + 32768 + r * 256;
        #pragma unroll
        for (int c = 0; c < 4; ++c) {
            uint32_t cc = ((uint32_t)(cbx + c) ^ ((r & 7) << 1)) * 16;
            cpasync16(base + cc,         g_pool + O_VTH + go + c * 8);
            cpasync16(base + 16384 + cc, g_pool + O_VTL + go + c * 8);
        }
    }
    CP_COMMIT();
}

__global__ __launch_bounds__(256, 1) void k_attn()
{
    extern __shared__ char smraw[];
    const uint32_t sb = smem_u32(smraw);
    const int qt = (int)gridDim.x - 1 - (int)blockIdx.x;
    const int bh = blockIdx.y;
    const int tid = threadIdx.x, lane = tid & 31, wid = tid >> 5;
    const int g = lane >> 2, tg = lane & 3;

    {
        const int r = tid >> 1, cbx = (tid & 1) * 4;
        const size_t go = ((size_t)bh * LSEQ + qt * 128 + r) * DHEAD + cbx * 8;
        const uint32_t base = sb + r * 128;
        #pragma unroll
        for (int c = 0; c < 4; ++c) {
            uint32_t cc = ((uint32_t)(cbx + c) ^ (r & 7)) * 16;
            cpasync16(base + cc,         g_pool + O_QH + go + c * 8);
            cpasync16(base + 16384 + cc, g_pool + O_QL + go + c * 8);
        }
        CP_COMMIT();
    }
    attn_load_kv(sb + 32768, bh, 0, tid);

    CP_WAIT(1);
    __syncthreads();

    uint32_t qh[4][4], ql[4][4];
    {
        int row = wid * 16 + (lane & 15);
        #pragma unroll
        for (int l = 0; l < 4; ++l) {
            int chunk = 2 * l + (lane >> 4);
            uint32_t a = sb + row * 128 + ((chunk ^ (row & 7)) * 16);
            LDSM4(qh[l][0], qh[l][1], qh[l][2], qh[l][3], a);
            LDSM4(ql[l][0], ql[l][1], ql[l][2], ql[l][3], a + 16384);
        }
    }

    float o[8][4];
    #pragma unroll
    for (int j = 0; j < 8; ++j)
        #pragma unroll
        for (int c = 0; c < 4; ++c) o[j][c] = 0.f;
    float den0 = 0.f, den1 = 0.f;

    const int rq = wid * 16 + g;

    int buf = 0;
    #pragma unroll 1
    for (int jt = 0; jt <= qt; ++jt) {
        if (jt < qt) { attn_load_kv(sb + 32768 + (buf ^ 1) * 65536, bh, jt + 1, tid); CP_WAIT(1); }
        else CP_WAIT(0);
        __syncthreads();
        const uint32_t sK = sb + 32768 + buf * 65536;
        const uint32_t sV = sK + 32768;

        const bool dg = (jt == qt);
        const int kkmax = dg ? wid : 7;

        #pragma unroll 1
        for (int kk = 0; kk <= kkmax; ++kk) {
            float s0[4] = {0.f, 0.f, 0.f, 0.f};
            float s1[4] = {0.f, 0.f, 0.f, 0.f};
            {
                int row = kk * 16 + (lane & 7) + ((lane >> 4) << 3);
                #pragma unroll
                for (int l = 0; l < 4; ++l) {
                    int chunk = 2 * l + ((lane >> 3) & 1);
                    uint32_t a = sK + row * 128 + ((chunk ^ (row & 7)) * 16);
                    uint32_t b0, b1, b2, b3, c0, c1, c2, c3;
                    LDSM4(b0, b1, b2, b3, a);
                    LDSM4(c0, c1, c2, c3, a + 16384);
                    MMA4(s0[0], s0[1], s0[2], s0[3], qh[l][0], qh[l][1], qh[l][2], qh[l][3], b0, b1);
                    MMA4(s0[0], s0[1], s0[2], s0[3], ql[l][0], ql[l][1], ql[l][2], ql[l][3], b0, b1);
                    MMA4(s0[0], s0[1], s0[2], s0[3], qh[l][0], qh[l][1], qh[l][2], qh[l][3], c0, c1);
                    MMA4(s1[0], s1[1], s1[2], s1[3], qh[l][0], qh[l][1], qh[l][2], qh[l][3], b2, b3);
                    MMA4(s1[0], s1[1], s1[2], s1[3], ql[l][0], ql[l][1], ql[l][2], ql[l][3], b2, b3);
                    MMA4(s1[0], s1[1], s1[2], s1[3], qh[l][0], qh[l][1], qh[l][2], qh[l][3], c2, c3);
                }
            }

            uint32_t p0, p1, p2, p3, r0, r1, r2, r3;
            {
                float e0 = fast_exp(s0[0] * 0.015625f);
                float e1 = fast_exp(s0[1] * 0.015625f);
                float e2 = fast_exp(s0[2] * 0.015625f);
                float e3 = fast_exp(s0[3] * 0.015625f);
                float f0 = fast_exp(s1[0] * 0.015625f);
                float f1 = fast_exp(s1[1] * 0.015625f);
                float f2 = fast_exp(s1[2] * 0.015625f);
                float f3 = fast_exp(s1[3] * 0.015625f);
                if (dg) {
                    int c0i = kk * 16 + 2 * tg;
                    if (c0i > rq)          e0 = 0.f;
                    if (c0i + 1 > rq)      e1 = 0.f;
                    if (c0i > rq + 8)      e2 = 0.f;
                    if (c0i + 1 > rq + 8)  e3 = 0.f;
                    if (c0i + 8 > rq)      f0 = 0.f;
                    if (c0i + 9 > rq)      f1 = 0.f;
                    if (c0i + 8 > rq + 8)  f2 = 0.f;
                    if (c0i + 9 > rq + 8)  f3 = 0.f;
                }
                den0 += e0 + e1 + f0 + f1;
                den1 += e2 + e3 + f2 + f3;
                float h0, l0, h1, l1;
                bsplit(e0, h0, l0); bsplit(e1, h1, l1);
                p0 = pack2(h0, h1); r0 = pack2(l0, l1);
                bsplit(e2, h0, l0); bsplit(e3, h1, l1);
                p1 = pack2(h0, h1); r1 = pack2(l0, l1);
                bsplit(f0, h0, l0); bsplit(f1, h1, l1);
                p2 = pack2(h0, h1); r2 = pack2(l0, l1);
                bsplit(f2, h0, l0); bsplit(f3, h1, l1);
                p3 = pack2(h0, h1); r3 = pack2(l0, l1);
            }

            {
                int row = (lane & 7) + ((lane >> 4) << 3);
                int chunk = 2 * kk + ((lane >> 3) & 1);
                #pragma unroll
                for (int np = 0; np < 4; ++np) {
                    int r2i = np * 16 + row;
                    uint32_t a = sV + r2i * 256 + ((chunk ^ ((r2i & 7) << 1)) * 16);
                    uint32_t vb0, vb1, vb2, vb3, vc0, vc1, vc2, vc3;
                    LDSM4(vb0, vb1, vb2, vb3, a);
                    LDSM4(vc0, vc1, vc2, vc3, a + 16384);
                    MMA4(o[2*np][0], o[2*np][1], o[2*np][2], o[2*np][3], p0, p1, p2, p3, vb0, vb1);
                    MMA4(o[2*np][0], o[2*np][1], o[2*np][2], o[2*np][3], r0, r1, r2, r3, vb0, vb1);
                    MMA4(o[2*np][0], o[2*np][1], o[2*np][2], o[2*np][3], p0, p1, p2, p3, vc0, vc1);
                    MMA4(o[2*np+1][0], o[2*np+1][1], o[2*np+1][2], o[2*np+1][3], p0, p1, p2, p3, vb2, vb3);
                    MMA4(o[2*np+1][0], o[2*np+1][1], o[2*np+1][2], o[2*np+1][3], r0, r1, r2, r3, vb2, vb3);
                    MMA4(o[2*np+1][0], o[2*np+1][1], o[2*np+1][2], o[2*np+1][3], p0, p1, p2, p3, vc2, vc3);
                }
            }
        }
        __syncthreads();
        buf ^= 1;
    }

    #pragma unroll
    for (int m = 1; m < 4; m <<= 1) {
        den0 += __shfl_xor_sync(0xffffffffu, den0, m);
        den1 += __shfl_xor_sync(0xffffffffu, den1, m);
    }
    const float inv0 = 1.f / den0, inv1 = 1.f / den1;

    const int b = bh >> 4, h = bh & 15;
    const size_t m0 = (size_t)b * LSEQ + qt * 128 + wid * 16 + g;
    u16* Yh = g_pool + O_YH;
    u16* Yl = g_pool + O_YL;
    #pragma unroll
    for (int j = 0; j < 8; ++j) {
        int d = j * 8 + 2 * tg;
        float h0, l0, h1, l1, h2, l2, h3, l3;
        bsplit(o[j][0] * inv0, h0, l0);
        bsplit(o[j][1] * inv0, h1, l1);
        bsplit(o[j][2] * inv1, h2, l2);
        bsplit(o[j][3] * inv1, h3, l3);
        *(uint32_t*)(Yh + m0 * DMODEL + h * 64 + d) = pack2(h0, h1);
        *(uint32_t*)(Yl + m0 * DMODEL + h * 64 + d) = pack2(l0, l1);
        *(uint32_t*)(Yh + (m0 + 8) * DMODEL + h * 64 + d) = pack2(h2, h3);
        *(uint32_t*)(Yl + (m0 + 8) * DMODEL + h * 64 + d) = pack2(l2, l3);
    }
}

// ---------------------------------------------------------------------------
extern "C" void kernel_launch(void* const* d_in, const int* in_sizes, int n_in,
                              void* d_out, int out_size)
{
    const float* X    = (const float*)d_in[0];
    const float* Wqk  = (const float*)d_in[1];
    const float* Wv   = (const float*)d_in[2];
    const float* Wout = (const float*)d_in[3];
    const float* qsc  = (const float*)d_in[4];
    const float* qbi  = (const float*)d_in[5];
    const float* ksc  = (const float*)d_in[6];
    const float* kbi  = (const float*)d_in[7];
    float* out = (float*)d_out;

    cudaFuncSetAttribute(k_qk_ln, cudaFuncAttributeMaxDynamicSharedMemorySize, PROJ_SMEM);
    cudaFuncSetAttribute(k_v,     cudaFuncAttributeMaxDynamicSharedMemorySize, KV_SMEM);
    cudaFuncSetAttribute(k_out,   cudaFuncAttributeMaxDynamicSharedMemorySize, KOUT_SMEM);
    cudaFuncSetAttribute(k_attn,  cudaFuncAttributeMaxDynamicSharedMemorySize, ATTN_SMEM);

    k_wsplit<<<2048, 256>>>(Wqk,  O_WQKH, O_WQKL, 2048 * 1024 / 4);
    k_wsplit<<<1024, 256>>>(Wv,   O_WVH,  O_WVL,  1024 * 1024 / 4);

    k_qk_ln<<<dim3(HEADS, MROWS / 128), 512, PROJ_SMEM>>>(X, qsc, qbi, ksc, kbi);
    k_v<<<dim3(8, MROWS / 128), 512, KV_SMEM>>>(X);
    k_attn<<<dim3(LSEQ / 128, BH), 256, ATTN_SMEM>>>();
    k_wsplit<<<1024, 256>>>(Wout, O_WOH, O_WOL, 1024 * 1024 / 4);
    k_out<<<dim3(8, MROWS / 128), 512, KOUT_SMEM>>>(out);
}